// round 1
// baseline (speedup 1.0000x reference)
#include <cuda_runtime.h>
#include <cstddef>

#define Bz 4
#define Sq 2048
#define Dm 512
#define Hh 8
#define DKh 64
#define Mrows (Bz*Sq)   // 8192

// ---------------- scratch (allocation-free: __device__ globals) ----------------
__device__ float g_q [Bz*Hh*Sq*DKh];   // (B,H,S,64)
__device__ float g_k [Bz*Hh*Sq*DKh];
__device__ float g_v [Bz*Hh*Sq*DKh];
__device__ float g_ao[Mrows*Dm];       // attention out, (B,S,D)
__device__ float g_fc[Mrows*Dm];       // fc + residual, pre-LN
__device__ float g_ew[Bz*Sq];          // 8 * exp(We[s]*entropy[b,s])

// ---------------- K0: entropy weights ----------------
__global__ void ew_kernel(const float* __restrict__ We, const float* __restrict__ ent) {
    int i = blockIdx.x * 256 + threadIdx.x;           // i < 8192
    int s = i & (Sq - 1);
    g_ew[i] = 8.0f * __expf(We[s] * ent[i]);          // scale=sqrt(64)=8 folded in
}

// ---------------- K1/K2/K3/K5: NT SGEMM  y[m][n] = sum_c A[m][c]*W[n][c] (+bias,(+res)) ----------------
// mode 0/1/2: scatter into g_q/g_k/g_v as (B,H,S,64).  mode 3: A=g_ao, +bias+resid -> g_fc.
__global__ __launch_bounds__(256) void gemm_nt(const float* __restrict__ A,
                                               const float* __restrict__ W,
                                               const float* __restrict__ bias,
                                               const float* __restrict__ resid,
                                               int mode) {
    __shared__ float At[16][132];   // k-major (transposed)
    __shared__ float Bt[16][68];

    const int t = threadIdx.x;
    const int tn = t & 15, tm = t >> 4;
    const int mbase = blockIdx.y * 128, nbase = blockIdx.x * 64;
    const float* Ap = (mode == 3) ? g_ao : A;

    float acc[8][4];
#pragma unroll
    for (int i = 0; i < 8; i++)
#pragma unroll
        for (int j = 0; j < 4; j++) acc[i][j] = 0.f;

    const int ar = t >> 2, ac = (t & 3) << 2;

    for (int k0 = 0; k0 < Dm; k0 += 16) {
        float4 a0 = *(const float4*)(Ap + (size_t)(mbase + ar) * Dm + k0 + ac);
        float4 a1 = *(const float4*)(Ap + (size_t)(mbase + ar + 64) * Dm + k0 + ac);
        float4 b0 = *(const float4*)(W  + (size_t)(nbase + ar) * Dm + k0 + ac);
        __syncthreads();
        At[ac + 0][ar] = a0.x; At[ac + 1][ar] = a0.y; At[ac + 2][ar] = a0.z; At[ac + 3][ar] = a0.w;
        At[ac + 0][ar + 64] = a1.x; At[ac + 1][ar + 64] = a1.y; At[ac + 2][ar + 64] = a1.z; At[ac + 3][ar + 64] = a1.w;
        Bt[ac + 0][ar] = b0.x; Bt[ac + 1][ar] = b0.y; Bt[ac + 2][ar] = b0.z; Bt[ac + 3][ar] = b0.w;
        __syncthreads();
#pragma unroll
        for (int kk = 0; kk < 16; kk++) {
            float4 p0 = *(float4*)&At[kk][tm * 8];
            float4 p1 = *(float4*)&At[kk][tm * 8 + 4];
            float4 q0 = *(float4*)&Bt[kk][tn * 4];
            float av[8] = {p0.x, p0.y, p0.z, p0.w, p1.x, p1.y, p1.z, p1.w};
            float bv[4] = {q0.x, q0.y, q0.z, q0.w};
#pragma unroll
            for (int i = 0; i < 8; i++)
#pragma unroll
                for (int j = 0; j < 4; j++) acc[i][j] = fmaf(av[i], bv[j], acc[i][j]);
        }
    }

    const int n0 = nbase + tn * 4;
    float bvl[4] = {bias[n0], bias[n0 + 1], bias[n0 + 2], bias[n0 + 3]};

    if (mode == 3) {
#pragma unroll
        for (int i = 0; i < 8; i++) {
            int m = mbase + tm * 8 + i;
            size_t o = (size_t)m * Dm + n0;
            float4 r = *(const float4*)(resid + o);
            float4 y = make_float4(acc[i][0] + bvl[0] + r.x, acc[i][1] + bvl[1] + r.y,
                                   acc[i][2] + bvl[2] + r.z, acc[i][3] + bvl[3] + r.w);
            *(float4*)(g_fc + o) = y;
        }
    } else {
        float* out = (mode == 0) ? g_q : ((mode == 1) ? g_k : g_v);
        const int h = nbase >> 6;        // BN=64 aligned with head width
        const int d0 = tn * 4;
#pragma unroll
        for (int i = 0; i < 8; i++) {
            int m = mbase + tm * 8 + i;
            int b_ = m >> 11, s_ = m & (Sq - 1);
            size_t o = (((size_t)(b_ * Hh + h)) * Sq + s_) * DKh + d0;
            float4 y = make_float4(acc[i][0] + bvl[0], acc[i][1] + bvl[1],
                                   acc[i][2] + bvl[2], acc[i][3] + bvl[3]);
            *(float4*)(out + o) = y;
        }
    }
}

// ---------------- K4: flash attention, fp32, Tq=128 Tk=64 ----------------
// grid (S/128, B*H), 256 threads = 16(tx:key/dim) x 16(ty:query)
#define ATT_SMEM_FLOATS (64*132 + 64*68 + 64*68 + 64*132 + 64)
#define ATT_SMEM_BYTES  (ATT_SMEM_FLOATS * 4)

__global__ __launch_bounds__(256, 1) void attn_kernel() {
    extern __shared__ float sm[];
    float* Qt  = sm;                    // [64 d][132]  (128 q + pad)
    float* Kt  = Qt + 64 * 132;         // [64 d][68]   (64 k + pad)
    float* Vs  = Kt + 64 * 68;          // [64 k][68]   (64 d + pad)
    float* Pt  = Vs + 64 * 68;          // [64 k][132]  (128 q + pad)
    float* ews = Pt + 64 * 132;         // [64]

    const int t  = threadIdx.x;
    const int tx = t & 15, ty = t >> 4;
    const int bh = blockIdx.y, b = bh >> 3, h = bh & 7;
    const int qbase = blockIdx.x * 128;

    const float* Qp  = g_q + (size_t)bh * Sq * DKh + (size_t)qbase * DKh;
    const float* Kp  = g_k + (size_t)bh * Sq * DKh;
    const float* Vp  = g_v + (size_t)bh * Sq * DKh;
    const float* ewp = g_ew + b * Sq;

    // load Q tile transposed into Qt[d][q]
    {
        int q = t >> 1, d0 = (t & 1) * 32;
#pragma unroll
        for (int u = 0; u < 8; u++) {
            float4 v = *(const float4*)(Qp + q * DKh + d0 + u * 4);
            Qt[(d0 + u * 4 + 0) * 132 + q] = v.x;
            Qt[(d0 + u * 4 + 1) * 132 + q] = v.y;
            Qt[(d0 + u * 4 + 2) * 132 + q] = v.z;
            Qt[(d0 + u * 4 + 3) * 132 + q] = v.w;
        }
    }

    float O[8][4], mcur[8], lsum[8];
#pragma unroll
    for (int i = 0; i < 8; i++) {
        mcur[i] = -1e30f; lsum[i] = 0.f;
#pragma unroll
        for (int j = 0; j < 4; j++) O[i][j] = 0.f;
    }

    for (int kt = 0; kt < Sq / 64; kt++) {
        __syncthreads();   // previous AV done reading Vs/Pt; Qt store done (iter 0)
        {
            int k = t >> 2, c0 = (t & 3) * 16;
            const float* kr = Kp + (size_t)(kt * 64 + k) * DKh;
            const float* vr = Vp + (size_t)(kt * 64 + k) * DKh;
#pragma unroll
            for (int u = 0; u < 4; u++) {
                int c = c0 + u * 4;
                float4 kv = *(const float4*)(kr + c);
                Kt[(c + 0) * 68 + k] = kv.x; Kt[(c + 1) * 68 + k] = kv.y;
                Kt[(c + 2) * 68 + k] = kv.z; Kt[(c + 3) * 68 + k] = kv.w;
                float4 vv = *(const float4*)(vr + c);
                *(float4*)&Vs[k * 68 + c] = vv;
            }
            if (t < 64) ews[t] = ewp[kt * 64 + t];
        }
        __syncthreads();

        // S = Q K^T  (fp32)
        float s[8][4];
#pragma unroll
        for (int i = 0; i < 8; i++)
#pragma unroll
            for (int j = 0; j < 4; j++) s[i][j] = 0.f;

#pragma unroll 4
        for (int d = 0; d < 64; d++) {
            float4 qa = *(float4*)&Qt[d * 132 + ty * 8];
            float4 qb = *(float4*)&Qt[d * 132 + ty * 8 + 4];
            float4 kk = *(float4*)&Kt[d * 68 + tx * 4];
            float qv[8] = {qa.x, qa.y, qa.z, qa.w, qb.x, qb.y, qb.z, qb.w};
            float kv[4] = {kk.x, kk.y, kk.z, kk.w};
#pragma unroll
            for (int i = 0; i < 8; i++)
#pragma unroll
                for (int j = 0; j < 4; j++) s[i][j] = fmaf(qv[i], kv[j], s[i][j]);
        }

        float ewf[4];
#pragma unroll
        for (int j = 0; j < 4; j++) ewf[j] = ews[tx * 4 + j];

        // online softmax (row = query); row-max all-reduced over the 16 tx lanes
#pragma unroll
        for (int i = 0; i < 8; i++) {
            float mt = -1e30f;
#pragma unroll
            for (int j = 0; j < 4; j++) { s[i][j] *= ewf[j]; mt = fmaxf(mt, s[i][j]); }
#pragma unroll
            for (int off = 1; off < 16; off <<= 1)
                mt = fmaxf(mt, __shfl_xor_sync(0xffffffffu, mt, off));
            float mn = fmaxf(mcur[i], mt);
            float alpha = __expf(mcur[i] - mn);
            mcur[i] = mn;
            float ps = 0.f;
#pragma unroll
            for (int j = 0; j < 4; j++) { float p = __expf(s[i][j] - mn); s[i][j] = p; ps += p; }
            lsum[i] = lsum[i] * alpha + ps;     // per-thread partial over own keys
#pragma unroll
            for (int j = 0; j < 4; j++) O[i][j] *= alpha;
        }

        // stage P transposed: Pt[k][q]
#pragma unroll
        for (int j = 0; j < 4; j++) {
            *(float4*)&Pt[(tx * 4 + j) * 132 + ty * 8]     = make_float4(s[0][j], s[1][j], s[2][j], s[3][j]);
            *(float4*)&Pt[(tx * 4 + j) * 132 + ty * 8 + 4] = make_float4(s[4][j], s[5][j], s[6][j], s[7][j]);
        }
        __syncthreads();

        // O += P V
#pragma unroll 4
        for (int k = 0; k < 64; k++) {
            float4 pa = *(float4*)&Pt[k * 132 + ty * 8];
            float4 pb = *(float4*)&Pt[k * 132 + ty * 8 + 4];
            float4 vv = *(float4*)&Vs[k * 68 + tx * 4];
            float pv[8] = {pa.x, pa.y, pa.z, pa.w, pb.x, pb.y, pb.z, pb.w};
            float vl[4] = {vv.x, vv.y, vv.z, vv.w};
#pragma unroll
            for (int i = 0; i < 8; i++)
#pragma unroll
                for (int j = 0; j < 4; j++) O[i][j] = fmaf(pv[i], vl[j], O[i][j]);
        }
    }

    // finalize: all-reduce row sums across tx, normalize, write (B,S,D)
#pragma unroll
    for (int i = 0; i < 8; i++) {
        float l = lsum[i];
#pragma unroll
        for (int off = 1; off < 16; off <<= 1) l += __shfl_xor_sync(0xffffffffu, l, off);
        float inv = 1.0f / l;
        float* orow = g_ao + ((size_t)(b * Sq + qbase + ty * 8 + i)) * Dm + h * DKh + tx * 4;
        *(float4*)orow = make_float4(O[i][0] * inv, O[i][1] * inv, O[i][2] * inv, O[i][3] * inv);
    }
}

// ---------------- K6: LayerNorm over D=512 ----------------
__global__ __launch_bounds__(128) void ln_kernel(const float* __restrict__ gamma,
                                                 const float* __restrict__ beta,
                                                 float* __restrict__ out) {
    __shared__ float red[4];
    const int row = blockIdx.x, t = threadIdx.x;
    float4 x = *(const float4*)(g_fc + (size_t)row * Dm + t * 4);
    float s = x.x + x.y + x.z + x.w;
#pragma unroll
    for (int off = 16; off > 0; off >>= 1) s += __shfl_xor_sync(0xffffffffu, s, off);
    if ((t & 31) == 0) red[t >> 5] = s;
    __syncthreads();
    float mu = (red[0] + red[1] + red[2] + red[3]) * (1.0f / Dm);
    float d0 = x.x - mu, d1 = x.y - mu, d2 = x.z - mu, d3 = x.w - mu;
    float sq = d0 * d0 + d1 * d1 + d2 * d2 + d3 * d3;
#pragma unroll
    for (int off = 16; off > 0; off >>= 1) sq += __shfl_xor_sync(0xffffffffu, sq, off);
    __syncthreads();
    if ((t & 31) == 0) red[t >> 5] = sq;
    __syncthreads();
    float var = (red[0] + red[1] + red[2] + red[3]) * (1.0f / Dm);
    float inv = rsqrtf(var + 1e-5f);
    int c = t * 4;
    float4 g  = *(const float4*)(gamma + c);
    float4 be = *(const float4*)(beta + c);
    *(float4*)(out + (size_t)row * Dm + c) =
        make_float4(d0 * inv * g.x + be.x, d1 * inv * g.y + be.y,
                    d2 * inv * g.z + be.z, d3 * inv * g.w + be.w);
}

// ---------------- launch ----------------
extern "C" void kernel_launch(void* const* d_in, const int* in_sizes, int n_in,
                              void* d_out, int out_size) {
    const float* Q    = (const float*)d_in[0];
    const float* K    = (const float*)d_in[1];
    const float* V    = (const float*)d_in[2];
    const float* ent  = (const float*)d_in[3];
    const float* Wq   = (const float*)d_in[4];
    const float* bq   = (const float*)d_in[5];
    const float* Wk   = (const float*)d_in[6];
    const float* bk   = (const float*)d_in[7];
    const float* Wv   = (const float*)d_in[8];
    const float* bv   = (const float*)d_in[9];
    const float* Wfc  = (const float*)d_in[10];
    const float* bfc  = (const float*)d_in[11];
    const float* We   = (const float*)d_in[12];
    const float* gam  = (const float*)d_in[13];
    const float* bet  = (const float*)d_in[14];
    float* out = (float*)d_out;

    cudaFuncSetAttribute(attn_kernel, cudaFuncAttributeMaxDynamicSharedMemorySize, ATT_SMEM_BYTES);

    ew_kernel<<<(Bz * Sq) / 256, 256>>>(We, ent);
    dim3 gg(Dm / 64, Mrows / 128);                 // (8, 64)
    gemm_nt<<<gg, 256>>>(Q, Wq, bq, nullptr, 0);
    gemm_nt<<<gg, 256>>>(K, Wk, bk, nullptr, 1);
    gemm_nt<<<gg, 256>>>(V, Wv, bv, nullptr, 2);
    attn_kernel<<<dim3(Sq / 128, Bz * Hh), 256, ATT_SMEM_BYTES>>>();
    gemm_nt<<<gg, 256>>>(nullptr, Wfc, bfc, Q, 3);
    ln_kernel<<<Mrows, 128>>>(gam, bet, out);
}

// round 9
// speedup vs baseline: 2.3667x; 2.3667x over previous
#include <cuda_runtime.h>
#include <cuda_bf16.h>
#include <cstdint>
#include <cstddef>

#define Bz 4
#define Sq 2048
#define Dm 512
#define Hh 8
#define DKh 64
#define Mrows (Bz*Sq)   // 8192

// ======================= scratch (__device__ globals) =======================
__device__ __nv_bfloat16 g_xq_hi[Mrows*Dm], g_xq_lo[Mrows*Dm];
__device__ __nv_bfloat16 g_xk_hi[Mrows*Dm], g_xk_lo[Mrows*Dm];
__device__ __nv_bfloat16 g_xv_hi[Mrows*Dm], g_xv_lo[Mrows*Dm];
__device__ __nv_bfloat16 g_wq_hi[Dm*Dm], g_wq_lo[Dm*Dm];
__device__ __nv_bfloat16 g_wk_hi[Dm*Dm], g_wk_lo[Dm*Dm];
__device__ __nv_bfloat16 g_wv_hi[Dm*Dm], g_wv_lo[Dm*Dm];
__device__ __nv_bfloat16 g_wf_hi[Dm*Dm], g_wf_lo[Dm*Dm];
__device__ __nv_bfloat16 g_qh_hi[Mrows*Dm], g_qh_lo[Mrows*Dm];   // (B,H,S,64)
__device__ __nv_bfloat16 g_kh_hi[Mrows*Dm], g_kh_lo[Mrows*Dm];   // (B,H,S,64)
__device__ __nv_bfloat16 g_vt_hi[Mrows*Dm], g_vt_lo[Mrows*Dm];   // (B,H,64,S)
__device__ __nv_bfloat16 g_ao_hi[Mrows*Dm], g_ao_lo[Mrows*Dm];   // (B,S,D)
__device__ float g_fc[Mrows*Dm];
__device__ float g_ew[Bz*Sq];

// ======================= helpers =======================
__device__ __forceinline__ uint32_t smem_u32(const void* p) {
    uint32_t a;
    asm("{ .reg .u64 t; cvta.to.shared.u64 t, %1; cvt.u32.u64 %0, t; }" : "=r"(a) : "l"(p));
    return a;
}
__device__ __forceinline__ void ldsm4(uint32_t* r, uint32_t addr) {
    asm volatile("ldmatrix.sync.aligned.m8n8.x4.shared.b16 {%0,%1,%2,%3}, [%4];"
        : "=r"(r[0]), "=r"(r[1]), "=r"(r[2]), "=r"(r[3]) : "r"(addr));
}
__device__ __forceinline__ void mma16816(float* d, const uint32_t* a, const uint32_t* b) {
    asm volatile("mma.sync.aligned.m16n8k16.row.col.f32.bf16.bf16.f32 "
        "{%0,%1,%2,%3}, {%4,%5,%6,%7}, {%8,%9}, {%0,%1,%2,%3};"
        : "+f"(d[0]), "+f"(d[1]), "+f"(d[2]), "+f"(d[3])
        : "r"(a[0]), "r"(a[1]), "r"(a[2]), "r"(a[3]), "r"(b[0]), "r"(b[1]));
}
// pack two floats into bf16x2 (v0 -> low half)
__device__ __forceinline__ uint32_t pk(float v0, float v1) {
    uint32_t r;
    asm("cvt.rn.bf16x2.f32 %0, %1, %2;" : "=r"(r) : "f"(v1), "f"(v0));
    return r;
}
__device__ __forceinline__ float resid_f(float v) {
    return v - __bfloat162float(__float2bfloat16(v));
}
__device__ __forceinline__ uint32_t pack_bf2(__nv_bfloat16 a, __nv_bfloat16 b) {
    __nv_bfloat162 v; v.x = a; v.y = b;
    return *reinterpret_cast<uint32_t*>(&v);
}

// ======================= K0: entropy weights =======================
__global__ void ew_kernel(const float* __restrict__ We, const float* __restrict__ ent) {
    int i = blockIdx.x * 256 + threadIdx.x;
    int s = i & (Sq - 1);
    g_ew[i] = 8.0f * __expf(We[s] * ent[i]);
}

// ======================= split fp32 -> bf16 hi/lo =======================
__global__ void split_kernel(const float* __restrict__ src, int which, int n4) {
    int i = blockIdx.x * 256 + threadIdx.x;
    if (i >= n4) return;
    __nv_bfloat16 *hi, *lo;
    switch (which) {
        case 0: hi = g_xq_hi; lo = g_xq_lo; break;
        case 1: hi = g_xk_hi; lo = g_xk_lo; break;
        case 2: hi = g_xv_hi; lo = g_xv_lo; break;
        case 3: hi = g_wq_hi; lo = g_wq_lo; break;
        case 4: hi = g_wk_hi; lo = g_wk_lo; break;
        case 5: hi = g_wv_hi; lo = g_wv_lo; break;
        default: hi = g_wf_hi; lo = g_wf_lo; break;
    }
    float4 v = ((const float4*)src)[i];
    __nv_bfloat16 h0 = __float2bfloat16(v.x), h1 = __float2bfloat16(v.y);
    __nv_bfloat16 h2 = __float2bfloat16(v.z), h3 = __float2bfloat16(v.w);
    __nv_bfloat16 l0 = __float2bfloat16(v.x - __bfloat162float(h0));
    __nv_bfloat16 l1 = __float2bfloat16(v.y - __bfloat162float(h1));
    __nv_bfloat16 l2 = __float2bfloat16(v.z - __bfloat162float(h2));
    __nv_bfloat16 l3 = __float2bfloat16(v.w - __bfloat162float(h3));
    ((uint2*)hi)[i] = make_uint2(pack_bf2(h0, h1), pack_bf2(h2, h3));
    ((uint2*)lo)[i] = make_uint2(pack_bf2(l0, l1), pack_bf2(l2, l3));
}

// ======================= GEMM: C[8192,512] = A * W^T (3-pass hi/lo) =======================
// CTA 128x128, BK=32, 8 warps (4x2), warp tile 32x64. No cp.async:
// LDG->reg prefetch, STS, one __syncthreads per chunk, double-buffered smem.
#define GP 80
#define GATILE 10240
#define GBUF 20480

__global__ __launch_bounds__(256) void gemm_tc(const float* __restrict__ bias,
                                               const float* __restrict__ resid,
                                               int mode) {
    __shared__ __align__(16) char sm[2 * GBUF];
    const int t = threadIdx.x, lane = t & 31, wid = t >> 5;
    const int wm = wid & 3, wn = wid >> 2;
    const int lr = lane >> 2, lc = lane & 3;
    const int mbase = blockIdx.y * 128, nbase = blockIdx.x * 128;

    const __nv_bfloat16 *Ah, *Al, *Wh, *Wl;
    switch (mode) {
        case 0: Ah = g_xq_hi; Al = g_xq_lo; Wh = g_wq_hi; Wl = g_wq_lo; break;
        case 1: Ah = g_xk_hi; Al = g_xk_lo; Wh = g_wk_hi; Wl = g_wk_lo; break;
        case 2: Ah = g_xv_hi; Al = g_xv_lo; Wh = g_wv_hi; Wl = g_wv_lo; break;
        default: Ah = g_ao_hi; Al = g_ao_lo; Wh = g_wf_hi; Wl = g_wf_lo; break;
    }

    float acc[2][8][4];
#pragma unroll
    for (int i = 0; i < 2; i++)
#pragma unroll
        for (int j = 0; j < 8; j++)
#pragma unroll
            for (int q = 0; q < 4; q++) acc[i][j][q] = 0.f;

    const int ld_row = t >> 2, ld_sg = t & 3;     // 64 rows x 4 segs per pass, x2

    uint4 ra[2], rb[2], na[2], nb[2];

    auto gload = [&](int c, uint4* A4, uint4* B4) {
        int pass = c >> 4, kk = (c & 15) * 32;
        const __nv_bfloat16* sa = (pass == 2) ? Al : Ah;
        const __nv_bfloat16* sb = (pass == 1) ? Wl : Wh;
        A4[0] = *(const uint4*)(sa + (size_t)(mbase + ld_row) * Dm + kk + ld_sg * 8);
        A4[1] = *(const uint4*)(sa + (size_t)(mbase + ld_row + 64) * Dm + kk + ld_sg * 8);
        B4[0] = *(const uint4*)(sb + (size_t)(nbase + ld_row) * Dm + kk + ld_sg * 8);
        B4[1] = *(const uint4*)(sb + (size_t)(nbase + ld_row + 64) * Dm + kk + ld_sg * 8);
    };

    gload(0, ra, rb);

    for (int c = 0; c < 48; c++) {
        char* as_ = sm + (c & 1) * GBUF;
        char* bs_ = as_ + GATILE;
        *(uint4*)(as_ + ld_row * GP + ld_sg * 16) = ra[0];
        *(uint4*)(as_ + (ld_row + 64) * GP + ld_sg * 16) = ra[1];
        *(uint4*)(bs_ + ld_row * GP + ld_sg * 16) = rb[0];
        *(uint4*)(bs_ + (ld_row + 64) * GP + ld_sg * 16) = rb[1];
        __syncthreads();
        if (c + 1 < 48) gload(c + 1, na, nb);

        uint32_t asu = smem_u32(as_), bsu = smem_u32(bs_);
#pragma unroll
        for (int ks = 0; ks < 2; ks++) {
            uint32_t af[2][4];
            ldsm4(af[0], asu + (wm * 32 + (lane & 15)) * GP + ks * 32 + (lane >> 4) * 16);
            ldsm4(af[1], asu + (wm * 32 + 16 + (lane & 15)) * GP + ks * 32 + (lane >> 4) * 16);
#pragma unroll
            for (int j2 = 0; j2 < 4; j2++) {
                uint32_t bf4[4];
                ldsm4(bf4, bsu + (wn * 64 + j2 * 16 + (lane & 15)) * GP + ks * 32 + (lane >> 4) * 16);
                uint32_t be[2] = {bf4[0], bf4[2]}, bo[2] = {bf4[1], bf4[3]};
#pragma unroll
                for (int i = 0; i < 2; i++) {
                    mma16816(acc[i][2 * j2],     af[i], be);
                    mma16816(acc[i][2 * j2 + 1], af[i], bo);
                }
            }
        }
        ra[0] = na[0]; ra[1] = na[1]; rb[0] = nb[0]; rb[1] = nb[1];
    }

    // epilogue
#pragma unroll
    for (int i = 0; i < 2; i++) {
        int m0 = mbase + wm * 32 + i * 16 + lr;
        int m1 = m0 + 8;
#pragma unroll
        for (int j = 0; j < 8; j++) {
            int n = nbase + wn * 64 + 8 * j + 2 * lc;
            float b0 = bias[n], b1 = bias[n + 1];
            float v0 = acc[i][j][0] + b0, v1 = acc[i][j][1] + b1;   // row m0
            float v2 = acc[i][j][2] + b0, v3 = acc[i][j][3] + b1;   // row m1
            if (mode == 3) {
                size_t o0 = (size_t)m0 * Dm + n, o1 = (size_t)m1 * Dm + n;
                float2 r0 = *(const float2*)(resid + o0);
                float2 r1 = *(const float2*)(resid + o1);
                *(float2*)(g_fc + o0) = make_float2(v0 + r0.x, v1 + r0.y);
                *(float2*)(g_fc + o1) = make_float2(v2 + r1.x, v3 + r1.y);
            } else if (mode == 2) {
                int h = n >> 6, dl = n & 63;
                int b0_ = m0 >> 11, s0 = m0 & (Sq - 1);
                int b1_ = m1 >> 11, s1 = m1 & (Sq - 1);
                size_t p00 = ((size_t)(b0_ * Hh + h) * DKh + dl) * Sq + s0;
                size_t p10 = ((size_t)(b1_ * Hh + h) * DKh + dl) * Sq + s1;
                g_vt_hi[p00] = __float2bfloat16(v0); g_vt_hi[p00 + Sq] = __float2bfloat16(v1);
                g_vt_lo[p00] = __float2bfloat16(resid_f(v0)); g_vt_lo[p00 + Sq] = __float2bfloat16(resid_f(v1));
                g_vt_hi[p10] = __float2bfloat16(v2); g_vt_hi[p10 + Sq] = __float2bfloat16(v3);
                g_vt_lo[p10] = __float2bfloat16(resid_f(v2)); g_vt_lo[p10 + Sq] = __float2bfloat16(resid_f(v3));
            } else {
                int h = n >> 6, dl = n & 63;
                int b0_ = m0 >> 11, s0 = m0 & (Sq - 1);
                int b1_ = m1 >> 11, s1 = m1 & (Sq - 1);
                size_t o0 = ((size_t)(b0_ * Hh + h) * Sq + s0) * DKh + dl;
                size_t o1 = ((size_t)(b1_ * Hh + h) * Sq + s1) * DKh + dl;
                __nv_bfloat16* oh = (mode == 0) ? g_qh_hi : g_kh_hi;
                __nv_bfloat16* ol = (mode == 0) ? g_qh_lo : g_kh_lo;
                *(uint32_t*)(oh + o0) = pk(v0, v1);
                *(uint32_t*)(ol + o0) = pk(resid_f(v0), resid_f(v1));
                *(uint32_t*)(oh + o1) = pk(v2, v3);
                *(uint32_t*)(ol + o1) = pk(resid_f(v2), resid_f(v3));
            }
        }
    }
}

// ======================= flash attention (mma.sync, 3-pass hi/lo) =======================
// grid (16, 32), 256 thr (8 warps). Tq=128 (warp: 16 rows), Tk=64, dk=64.
// FULL key loop: Sq/64 = 32 iterations.
// No cp.async: LDG->reg prefetch + STS, one sync per k-tile, double-buffered smem.
#define AP 144
#define ATS 9216          // one tile: 64*144
#define ABUF 36864        // 4 tiles
#define A_BASE 512
#define AT_SMEM (A_BASE + 2*ABUF)   // 74240
#define NKT (Sq/64)       // 32

__global__ __launch_bounds__(256, 1) void attn_tc() {
    extern __shared__ char smA[];
    const uint32_t smu = smem_u32(smA);
    const int t = threadIdx.x, lane = t & 31, wid = t >> 5;
    const int lr = lane >> 2, lc = lane & 3;
    const int bh = blockIdx.y, b = bh >> 3;
    const int qbase = blockIdx.x * 128;

    // ---- stage Q (hi/lo) into buffer-1 area, load into registers ----
    {
        char* qdst = smA + A_BASE + ABUF;
#pragma unroll
        for (int i = 0; i < 8; i++) {
            int id = t + i * 256;
            int half = id >> 10, w = id & 1023, row = w >> 3, sg = w & 7;
            const __nv_bfloat16* src = half ? g_qh_lo : g_qh_hi;
            *(uint4*)(qdst + half * (64 * AP * 2) + row * AP + sg * 16) =
                *(const uint4*)(src + ((size_t)bh * Sq + qbase + row) * DKh + sg * 8);
        }
    }
    __syncthreads();

    uint32_t qhf[4][4], qlf[4][4];
    {
        uint32_t qb = smu + A_BASE + ABUF + (wid * 16 + (lane & 15)) * AP + (lane >> 4) * 16;
#pragma unroll
        for (int ks = 0; ks < 4; ks++) {
            ldsm4(qhf[ks], qb + ks * 32);
            ldsm4(qlf[ks], qb + ks * 32 + 64 * AP * 2);
        }
    }
    __syncthreads();

    uint4 rv[8], nv[8];
    float rew = 0.f, newv = 0.f;

    auto aload = [&](int kt, uint4* R, float& E) {
#pragma unroll
        for (int i = 0; i < 8; i++) {
            int id = t + i * 256;
            int tile = id >> 9, w = id & 511, row = w >> 3, sg = w & 7;
            const __nv_bfloat16* src;
            size_t g;
            if (tile == 0)      { src = g_kh_hi; g = ((size_t)bh * Sq + kt * 64 + row) * DKh + sg * 8; }
            else if (tile == 1) { src = g_kh_lo; g = ((size_t)bh * Sq + kt * 64 + row) * DKh + sg * 8; }
            else if (tile == 2) { src = g_vt_hi; g = ((size_t)bh * DKh + row) * Sq + kt * 64 + sg * 8; }
            else                { src = g_vt_lo; g = ((size_t)bh * DKh + row) * Sq + kt * 64 + sg * 8; }
            R[i] = *(const uint4*)(src + g);
        }
        if (t < 64) E = g_ew[(size_t)b * Sq + kt * 64 + t];
    };
    auto astore = [&](int kt, const uint4* R, float E) {
        char* dst = smA + A_BASE + (kt & 1) * ABUF;
#pragma unroll
        for (int i = 0; i < 8; i++) {
            int id = t + i * 256;
            int tile = id >> 9, w = id & 511, row = w >> 3, sg = w & 7;
            *(uint4*)(dst + tile * ATS + row * AP + sg * 16) = R[i];
        }
        if (t < 64) *(float*)(smA + (kt & 1) * 256 + t * 4) = E;
    };

    float O[8][4];
#pragma unroll
    for (int j = 0; j < 8; j++)
#pragma unroll
        for (int q = 0; q < 4; q++) O[j][q] = 0.f;
    float m0 = -1e30f, m1 = -1e30f, l0 = 0.f, l1 = 0.f;

    aload(0, rv, rew);

    for (int kt = 0; kt < NKT; kt++) {
        astore(kt, rv, rew);
        __syncthreads();
        if (kt + 1 < NKT) aload(kt + 1, nv, newv);

        uint32_t bK = smu + A_BASE + (kt & 1) * ABUF;

        // ---- S = Q K^T (3-pass) ----
        float S[8][4];
#pragma unroll
        for (int j = 0; j < 8; j++)
#pragma unroll
            for (int q = 0; q < 4; q++) S[j][q] = 0.f;

#pragma unroll
        for (int p = 0; p < 3; p++) {
            uint32_t kb = bK + ((p == 1) ? (uint32_t)ATS : 0u)
                        + ((lane & 15)) * AP + (lane >> 4) * 16;
            const uint32_t (*QF)[4] = (p == 2) ? qlf : qhf;
#pragma unroll
            for (int ks = 0; ks < 4; ks++) {
#pragma unroll
                for (int j2 = 0; j2 < 4; j2++) {
                    uint32_t bf4[4];
                    ldsm4(bf4, kb + j2 * 16 * AP + ks * 32);
                    uint32_t be[2] = {bf4[0], bf4[2]}, bo[2] = {bf4[1], bf4[3]};
                    mma16816(S[2 * j2],     QF[ks], be);
                    mma16816(S[2 * j2 + 1], QF[ks], bo);
                }
            }
        }

        // ---- softmax (rows lr and lr+8, cols spread over 4 lanes) ----
        const float* ew = (const float*)(smA + (kt & 1) * 256);
        float mt0 = -1e30f, mt1 = -1e30f;
#pragma unroll
        for (int j = 0; j < 8; j++) {
            float2 e = *(const float2*)(ew + 8 * j + 2 * lc);
            S[j][0] *= e.x; S[j][1] *= e.y;
            S[j][2] *= e.x; S[j][3] *= e.y;
            mt0 = fmaxf(mt0, fmaxf(S[j][0], S[j][1]));
            mt1 = fmaxf(mt1, fmaxf(S[j][2], S[j][3]));
        }
        mt0 = fmaxf(mt0, __shfl_xor_sync(0xffffffffu, mt0, 1));
        mt0 = fmaxf(mt0, __shfl_xor_sync(0xffffffffu, mt0, 2));
        mt1 = fmaxf(mt1, __shfl_xor_sync(0xffffffffu, mt1, 1));
        mt1 = fmaxf(mt1, __shfl_xor_sync(0xffffffffu, mt1, 2));
        float mn0 = fmaxf(m0, mt0), mn1 = fmaxf(m1, mt1);
        float al0 = __expf(m0 - mn0), al1 = __expf(m1 - mn1);
        m0 = mn0; m1 = mn1;
        float ps0 = 0.f, ps1 = 0.f;
#pragma unroll
        for (int j = 0; j < 8; j++) {
            S[j][0] = __expf(S[j][0] - mn0); ps0 += S[j][0];
            S[j][1] = __expf(S[j][1] - mn0); ps0 += S[j][1];
            S[j][2] = __expf(S[j][2] - mn1); ps1 += S[j][2];
            S[j][3] = __expf(S[j][3] - mn1); ps1 += S[j][3];
        }
        ps0 += __shfl_xor_sync(0xffffffffu, ps0, 1);
        ps0 += __shfl_xor_sync(0xffffffffu, ps0, 2);
        ps1 += __shfl_xor_sync(0xffffffffu, ps1, 1);
        ps1 += __shfl_xor_sync(0xffffffffu, ps1, 2);
        l0 = l0 * al0 + ps0;
        l1 = l1 * al1 + ps1;
#pragma unroll
        for (int j = 0; j < 8; j++) {
            O[j][0] *= al0; O[j][1] *= al0;
            O[j][2] *= al1; O[j][3] *= al1;
        }

        // ---- P packs (hi/lo), reused directly as mma A operands ----
        uint32_t Ph[8][2], Pl[8][2];
#pragma unroll
        for (int j = 0; j < 8; j++) {
            Ph[j][0] = pk(S[j][0], S[j][1]);
            Ph[j][1] = pk(S[j][2], S[j][3]);
            Pl[j][0] = pk(resid_f(S[j][0]), resid_f(S[j][1]));
            Pl[j][1] = pk(resid_f(S[j][2]), resid_f(S[j][3]));
        }

        // ---- O += P V (3-pass) ----
#pragma unroll
        for (int p = 0; p < 3; p++) {
            uint32_t vb = bK + 2 * ATS + ((p == 1) ? (uint32_t)ATS : 0u)
                        + ((lane & 15)) * AP + (lane >> 4) * 16;
            const uint32_t (*PF)[2] = (p == 2) ? Pl : Ph;
#pragma unroll
            for (int ks = 0; ks < 4; ks++) {
                uint32_t a4[4] = {PF[2 * ks][0], PF[2 * ks][1], PF[2 * ks + 1][0], PF[2 * ks + 1][1]};
#pragma unroll
                for (int j2 = 0; j2 < 4; j2++) {
                    uint32_t vf[4];
                    ldsm4(vf, vb + j2 * 16 * AP + ks * 32);
                    uint32_t ve[2] = {vf[0], vf[2]}, vo[2] = {vf[1], vf[3]};
                    mma16816(O[2 * j2],     a4, ve);
                    mma16816(O[2 * j2 + 1], a4, vo);
                }
            }
        }

#pragma unroll
        for (int i = 0; i < 8; i++) rv[i] = nv[i];
        rew = newv;
    }

    // ---- finalize + write hi/lo into (B,S,512) ----
    float inv0 = 1.0f / l0, inv1 = 1.0f / l1;
    int row0 = qbase + wid * 16 + lr, row1 = row0 + 8;
    size_t base0 = ((size_t)(b * Sq + row0)) * Dm + (bh & 7) * DKh + 2 * lc;
    size_t base1 = ((size_t)(b * Sq + row1)) * Dm + (bh & 7) * DKh + 2 * lc;
#pragma unroll
    for (int j = 0; j < 8; j++) {
        float v0 = O[j][0] * inv0, v1 = O[j][1] * inv0;
        float v2 = O[j][2] * inv1, v3 = O[j][3] * inv1;
        *(uint32_t*)(g_ao_hi + base0 + 8 * j) = pk(v0, v1);
        *(uint32_t*)(g_ao_lo + base0 + 8 * j) = pk(resid_f(v0), resid_f(v1));
        *(uint32_t*)(g_ao_hi + base1 + 8 * j) = pk(v2, v3);
        *(uint32_t*)(g_ao_lo + base1 + 8 * j) = pk(resid_f(v2), resid_f(v3));
    }
}

// ======================= LayerNorm =======================
__global__ __launch_bounds__(128) void ln_kernel(const float* __restrict__ gamma,
                                                 const float* __restrict__ beta,
                                                 float* __restrict__ out) {
    __shared__ float red[4];
    const int row = blockIdx.x, t = threadIdx.x;
    float4 x = *(const float4*)(g_fc + (size_t)row * Dm + t * 4);
    float s = x.x + x.y + x.z + x.w;
#pragma unroll
    for (int off = 16; off > 0; off >>= 1) s += __shfl_xor_sync(0xffffffffu, s, off);
    if ((t & 31) == 0) red[t >> 5] = s;
    __syncthreads();
    float mu = (red[0] + red[1] + red[2] + red[3]) * (1.0f / Dm);
    float d0 = x.x - mu, d1 = x.y - mu, d2 = x.z - mu, d3 = x.w - mu;
    float sq = d0 * d0 + d1 * d1 + d2 * d2 + d3 * d3;
#pragma unroll
    for (int off = 16; off > 0; off >>= 1) sq += __shfl_xor_sync(0xffffffffu, sq, off);
    __syncthreads();
    if ((t & 31) == 0) red[t >> 5] = sq;
    __syncthreads();
    float var = (red[0] + red[1] + red[2] + red[3]) * (1.0f / Dm);
    float inv = rsqrtf(var + 1e-5f);
    int c = t * 4;
    float4 g = *(const float4*)(gamma + c);
    float4 be = *(const float4*)(beta + c);
    *(float4*)(out + (size_t)row * Dm + c) =
        make_float4(d0 * inv * g.x + be.x, d1 * inv * g.y + be.y,
                    d2 * inv * g.z + be.z, d3 * inv * g.w + be.w);
}

// ======================= launch =======================
extern "C" void kernel_launch(void* const* d_in, const int* in_sizes, int n_in,
                              void* d_out, int out_size) {
    const float* Q   = (const float*)d_in[0];
    const float* K   = (const float*)d_in[1];
    const float* V   = (const float*)d_in[2];
    const float* ent = (const float*)d_in[3];
    const float* Wq  = (const float*)d_in[4];
    const float* bq  = (const float*)d_in[5];
    const float* Wk  = (const float*)d_in[6];
    const float* bk  = (const float*)d_in[7];
    const float* Wv  = (const float*)d_in[8];
    const float* bv  = (const float*)d_in[9];
    const float* Wfc = (const float*)d_in[10];
    const float* bfc = (const float*)d_in[11];
    const float* We  = (const float*)d_in[12];
    const float* gam = (const float*)d_in[13];
    const float* bet = (const float*)d_in[14];
    float* out = (float*)d_out;

    cudaFuncSetAttribute(attn_tc, cudaFuncAttributeMaxDynamicSharedMemorySize, AT_SMEM);

    ew_kernel<<<(Bz * Sq) / 256, 256>>>(We, ent);
    split_kernel<<<4096, 256>>>(Q, 0, Mrows * Dm / 4);
    split_kernel<<<4096, 256>>>(K, 1, Mrows * Dm / 4);
    split_kernel<<<4096, 256>>>(V, 2, Mrows * Dm / 4);
    split_kernel<<<256, 256>>>(Wq, 3, Dm * Dm / 4);
    split_kernel<<<256, 256>>>(Wk, 4, Dm * Dm / 4);
    split_kernel<<<256, 256>>>(Wv, 5, Dm * Dm / 4);
    split_kernel<<<256, 256>>>(Wfc, 6, Dm * Dm / 4);

    dim3 gg(Dm / 128, Mrows / 128);   // (4, 64)
    gemm_tc<<<gg, 256>>>(bq, nullptr, 0);
    gemm_tc<<<gg, 256>>>(bk, nullptr, 1);
    gemm_tc<<<gg, 256>>>(bv, nullptr, 2);

    attn_tc<<<dim3(Sq / 128, Bz * Hh), 256, AT_SMEM>>>();

    gemm_tc<<<gg, 256>>>(bfc, Q, 3);
    ln_kernel<<<Mrows, 128>>>(gam, bet, out);
}

// round 10
// speedup vs baseline: 2.4888x; 1.0516x over previous
#include <cuda_runtime.h>
#include <cuda_bf16.h>
#include <cstdint>
#include <cstddef>

#define Bz 4
#define Sq 2048
#define Dm 512
#define Hh 8
#define DKh 64
#define Mrows (Bz*Sq)   // 8192

// ======================= scratch (__device__ globals) =======================
__device__ __nv_bfloat16 g_xq_hi[Mrows*Dm], g_xq_lo[Mrows*Dm];
__device__ __nv_bfloat16 g_xk_hi[Mrows*Dm], g_xk_lo[Mrows*Dm];
__device__ __nv_bfloat16 g_xv_hi[Mrows*Dm], g_xv_lo[Mrows*Dm];
__device__ __nv_bfloat16 g_wq_hi[Dm*Dm], g_wq_lo[Dm*Dm];
__device__ __nv_bfloat16 g_wk_hi[Dm*Dm], g_wk_lo[Dm*Dm];
__device__ __nv_bfloat16 g_wv_hi[Dm*Dm], g_wv_lo[Dm*Dm];
__device__ __nv_bfloat16 g_wf_hi[Dm*Dm], g_wf_lo[Dm*Dm];
__device__ __nv_bfloat16 g_qh_hi[Mrows*Dm], g_qh_lo[Mrows*Dm];   // (B,H,S,64)
__device__ __nv_bfloat16 g_kh_hi[Mrows*Dm], g_kh_lo[Mrows*Dm];   // (B,H,S,64)
__device__ __nv_bfloat16 g_vt_hi[Mrows*Dm], g_vt_lo[Mrows*Dm];   // (B,H,64,S)
__device__ __nv_bfloat16 g_ao_hi[Mrows*Dm], g_ao_lo[Mrows*Dm];   // (B,S,D)
__device__ float g_fc[Mrows*Dm];
__device__ float g_ew[Bz*Sq];

// ======================= helpers =======================
__device__ __forceinline__ uint32_t smem_u32(const void* p) {
    uint32_t a;
    asm("{ .reg .u64 t; cvta.to.shared.u64 t, %1; cvt.u32.u64 %0, t; }" : "=r"(a) : "l"(p));
    return a;
}
__device__ __forceinline__ void ldsm4(uint32_t* r, uint32_t addr) {
    asm volatile("ldmatrix.sync.aligned.m8n8.x4.shared.b16 {%0,%1,%2,%3}, [%4];"
        : "=r"(r[0]), "=r"(r[1]), "=r"(r[2]), "=r"(r[3]) : "r"(addr));
}
__device__ __forceinline__ void mma16816(float* d, const uint32_t* a, const uint32_t* b) {
    asm volatile("mma.sync.aligned.m16n8k16.row.col.f32.bf16.bf16.f32 "
        "{%0,%1,%2,%3}, {%4,%5,%6,%7}, {%8,%9}, {%0,%1,%2,%3};"
        : "+f"(d[0]), "+f"(d[1]), "+f"(d[2]), "+f"(d[3])
        : "r"(a[0]), "r"(a[1]), "r"(a[2]), "r"(a[3]), "r"(b[0]), "r"(b[1]));
}
// pack two floats into bf16x2 (v0 -> low half)
__device__ __forceinline__ uint32_t pk(float v0, float v1) {
    uint32_t r;
    asm("cvt.rn.bf16x2.f32 %0, %1, %2;" : "=r"(r) : "f"(v1), "f"(v0));
    return r;
}
__device__ __forceinline__ float resid_f(float v) {
    return v - __bfloat162float(__float2bfloat16(v));
}
__device__ __forceinline__ uint32_t pack_bf2(__nv_bfloat16 a, __nv_bfloat16 b) {
    __nv_bfloat162 v; v.x = a; v.y = b;
    return *reinterpret_cast<uint32_t*>(&v);
}

// ======================= K0: entropy weights =======================
__global__ void ew_kernel(const float* __restrict__ We, const float* __restrict__ ent) {
    int i = blockIdx.x * 256 + threadIdx.x;
    int s = i & (Sq - 1);
    g_ew[i] = 8.0f * __expf(We[s] * ent[i]);
}

// ======================= split fp32 -> bf16 hi/lo =======================
__global__ void split_kernel(const float* __restrict__ src, int which, int n4) {
    int i = blockIdx.x * 256 + threadIdx.x;
    if (i >= n4) return;
    __nv_bfloat16 *hi, *lo;
    switch (which) {
        case 0: hi = g_xq_hi; lo = g_xq_lo; break;
        case 1: hi = g_xk_hi; lo = g_xk_lo; break;
        case 2: hi = g_xv_hi; lo = g_xv_lo; break;
        case 3: hi = g_wq_hi; lo = g_wq_lo; break;
        case 4: hi = g_wk_hi; lo = g_wk_lo; break;
        case 5: hi = g_wv_hi; lo = g_wv_lo; break;
        default: hi = g_wf_hi; lo = g_wf_lo; break;
    }
    float4 v = ((const float4*)src)[i];
    __nv_bfloat16 h0 = __float2bfloat16(v.x), h1 = __float2bfloat16(v.y);
    __nv_bfloat16 h2 = __float2bfloat16(v.z), h3 = __float2bfloat16(v.w);
    __nv_bfloat16 l0 = __float2bfloat16(v.x - __bfloat162float(h0));
    __nv_bfloat16 l1 = __float2bfloat16(v.y - __bfloat162float(h1));
    __nv_bfloat16 l2 = __float2bfloat16(v.z - __bfloat162float(h2));
    __nv_bfloat16 l3 = __float2bfloat16(v.w - __bfloat162float(h3));
    ((uint2*)hi)[i] = make_uint2(pack_bf2(h0, h1), pack_bf2(h2, h3));
    ((uint2*)lo)[i] = make_uint2(pack_bf2(l0, l1), pack_bf2(l2, l3));
}

// ======================= GEMM: C[8192,512] = A * W^T (fused 3-pass hi/lo) =======================
// CTA 128x128, BK=32, 8 warps (4x2), warp tile 32x64. Single K sweep: all 4 tiles
// {Ah,Al,Wh,Wl} staged per chunk; each B fragment ldsm'd once, fed to 2 A operands.
#define GP 80
#define GTILE 10240       // 128 rows x 80B
#define GBUF  (4*GTILE)   // 40960
#define GSMEM (2*GBUF)    // 81920

__global__ __launch_bounds__(256, 1) void gemm_tc(const float* __restrict__ bias,
                                                  const float* __restrict__ resid,
                                                  int mode) {
    extern __shared__ __align__(16) char gsm[];
    const int t = threadIdx.x, lane = t & 31, wid = t >> 5;
    const int wm = wid & 3, wn = wid >> 2;
    const int lr = lane >> 2, lc = lane & 3;
    const int mbase = blockIdx.y * 128, nbase = blockIdx.x * 128;

    const __nv_bfloat16 *Ah, *Al, *Wh, *Wl;
    switch (mode) {
        case 0: Ah = g_xq_hi; Al = g_xq_lo; Wh = g_wq_hi; Wl = g_wq_lo; break;
        case 1: Ah = g_xk_hi; Al = g_xk_lo; Wh = g_wk_hi; Wl = g_wk_lo; break;
        case 2: Ah = g_xv_hi; Al = g_xv_lo; Wh = g_wv_hi; Wl = g_wv_lo; break;
        default: Ah = g_ao_hi; Al = g_ao_lo; Wh = g_wf_hi; Wl = g_wf_lo; break;
    }

    float acc[2][8][4];
#pragma unroll
    for (int i = 0; i < 2; i++)
#pragma unroll
        for (int j = 0; j < 8; j++)
#pragma unroll
            for (int q = 0; q < 4; q++) acc[i][j][q] = 0.f;

    uint4 rr[8], nn[8];

    auto gload = [&](int c, uint4* R) {
        int kk = c * 32;
#pragma unroll
        for (int i = 0; i < 8; i++) {
            int id = t + i * 256;
            int tile = id >> 9, w = id & 511, row = w >> 2, sg = w & 3;
            const __nv_bfloat16* src = (tile == 0) ? Ah : (tile == 1) ? Al : (tile == 2) ? Wh : Wl;
            int base = (tile < 2) ? mbase : nbase;
            R[i] = *(const uint4*)(src + (size_t)(base + row) * Dm + kk + sg * 8);
        }
    };
    auto gstore = [&](int c, const uint4* R) {
        char* buf = gsm + (c & 1) * GBUF;
#pragma unroll
        for (int i = 0; i < 8; i++) {
            int id = t + i * 256;
            int tile = id >> 9, w = id & 511, row = w >> 2, sg = w & 3;
            *(uint4*)(buf + tile * GTILE + row * GP + sg * 16) = R[i];
        }
    };

    gload(0, rr);

    for (int c = 0; c < 16; c++) {
        gstore(c, rr);
        __syncthreads();
        if (c + 1 < 16) gload(c + 1, nn);

        uint32_t bufu = smem_u32(gsm + (c & 1) * GBUF);
#pragma unroll
        for (int ks = 0; ks < 2; ks++) {
            uint32_t afh[2][4], afl[2][4];
            uint32_t arow = bufu + (wm * 32 + (lane & 15)) * GP + ks * 32 + (lane >> 4) * 16;
            ldsm4(afh[0], arow);
            ldsm4(afh[1], arow + 16 * GP);
            ldsm4(afl[0], arow + GTILE);
            ldsm4(afl[1], arow + GTILE + 16 * GP);
            uint32_t brow = bufu + 2 * GTILE + (wn * 64 + (lane & 15)) * GP + ks * 32 + (lane >> 4) * 16;
#pragma unroll
            for (int j2 = 0; j2 < 4; j2++) {
                uint32_t wh4[4];
                ldsm4(wh4, brow + j2 * 16 * GP);
                {
                    uint32_t be[2] = {wh4[0], wh4[2]}, bo[2] = {wh4[1], wh4[3]};
#pragma unroll
                    for (int i = 0; i < 2; i++) {
                        mma16816(acc[i][2 * j2],     afh[i], be);
                        mma16816(acc[i][2 * j2 + 1], afh[i], bo);
                        mma16816(acc[i][2 * j2],     afl[i], be);
                        mma16816(acc[i][2 * j2 + 1], afl[i], bo);
                    }
                }
                uint32_t wl4[4];
                ldsm4(wl4, brow + GTILE + j2 * 16 * GP);
                {
                    uint32_t be[2] = {wl4[0], wl4[2]}, bo[2] = {wl4[1], wl4[3]};
#pragma unroll
                    for (int i = 0; i < 2; i++) {
                        mma16816(acc[i][2 * j2],     afh[i], be);
                        mma16816(acc[i][2 * j2 + 1], afh[i], bo);
                    }
                }
            }
        }
#pragma unroll
        for (int i = 0; i < 8; i++) rr[i] = nn[i];
    }

    // epilogue
#pragma unroll
    for (int i = 0; i < 2; i++) {
        int m0 = mbase + wm * 32 + i * 16 + lr;
        int m1 = m0 + 8;
#pragma unroll
        for (int j = 0; j < 8; j++) {
            int n = nbase + wn * 64 + 8 * j + 2 * lc;
            float b0 = bias[n], b1 = bias[n + 1];
            float v0 = acc[i][j][0] + b0, v1 = acc[i][j][1] + b1;   // row m0
            float v2 = acc[i][j][2] + b0, v3 = acc[i][j][3] + b1;   // row m1
            if (mode == 3) {
                size_t o0 = (size_t)m0 * Dm + n, o1 = (size_t)m1 * Dm + n;
                float2 r0 = *(const float2*)(resid + o0);
                float2 r1 = *(const float2*)(resid + o1);
                *(float2*)(g_fc + o0) = make_float2(v0 + r0.x, v1 + r0.y);
                *(float2*)(g_fc + o1) = make_float2(v2 + r1.x, v3 + r1.y);
            } else if (mode == 2) {
                int h = n >> 6, dl = n & 63;
                int b0_ = m0 >> 11, s0 = m0 & (Sq - 1);
                int b1_ = m1 >> 11, s1 = m1 & (Sq - 1);
                size_t p00 = ((size_t)(b0_ * Hh + h) * DKh + dl) * Sq + s0;
                size_t p10 = ((size_t)(b1_ * Hh + h) * DKh + dl) * Sq + s1;
                g_vt_hi[p00] = __float2bfloat16(v0); g_vt_hi[p00 + Sq] = __float2bfloat16(v1);
                g_vt_lo[p00] = __float2bfloat16(resid_f(v0)); g_vt_lo[p00 + Sq] = __float2bfloat16(resid_f(v1));
                g_vt_hi[p10] = __float2bfloat16(v2); g_vt_hi[p10 + Sq] = __float2bfloat16(v3);
                g_vt_lo[p10] = __float2bfloat16(resid_f(v2)); g_vt_lo[p10 + Sq] = __float2bfloat16(resid_f(v3));
            } else {
                int h = n >> 6, dl = n & 63;
                int b0_ = m0 >> 11, s0 = m0 & (Sq - 1);
                int b1_ = m1 >> 11, s1 = m1 & (Sq - 1);
                size_t o0 = ((size_t)(b0_ * Hh + h) * Sq + s0) * DKh + dl;
                size_t o1 = ((size_t)(b1_ * Hh + h) * Sq + s1) * DKh + dl;
                __nv_bfloat16* oh = (mode == 0) ? g_qh_hi : g_kh_hi;
                __nv_bfloat16* ol = (mode == 0) ? g_qh_lo : g_kh_lo;
                *(uint32_t*)(oh + o0) = pk(v0, v1);
                *(uint32_t*)(ol + o0) = pk(resid_f(v0), resid_f(v1));
                *(uint32_t*)(oh + o1) = pk(v2, v3);
                *(uint32_t*)(ol + o1) = pk(resid_f(v2), resid_f(v3));
            }
        }
    }
}

// ======================= flash attention (mma.sync, fused 3-pass hi/lo) =======================
// grid (16, 32), 256 thr (8 warps). Tq=128 (warp: 16 rows), Tk=64, dk=64.
// Each K/V fragment ldsm'd ONCE and fed to both hi/lo A operands.
#define AP 144
#define ATS 9216          // one tile: 64*144
#define ABUF 36864        // 4 tiles
#define A_BASE 512
#define AT_SMEM (A_BASE + 2*ABUF)   // 74240
#define NKT (Sq/64)       // 32

__global__ __launch_bounds__(256, 1) void attn_tc() {
    extern __shared__ char smA[];
    const uint32_t smu = smem_u32(smA);
    const int t = threadIdx.x, lane = t & 31, wid = t >> 5;
    const int lr = lane >> 2, lc = lane & 3;
    const int bh = blockIdx.y, b = bh >> 3;
    const int qbase = blockIdx.x * 128;

    // ---- stage Q (hi/lo) into buffer-1 area, load into registers ----
    {
        char* qdst = smA + A_BASE + ABUF;
#pragma unroll
        for (int i = 0; i < 8; i++) {
            int id = t + i * 256;
            int half = id >> 10, w = id & 1023, row = w >> 3, sg = w & 7;
            const __nv_bfloat16* src = half ? g_qh_lo : g_qh_hi;
            *(uint4*)(qdst + half * (64 * AP * 2) + row * AP + sg * 16) =
                *(const uint4*)(src + ((size_t)bh * Sq + qbase + row) * DKh + sg * 8);
        }
    }
    __syncthreads();

    uint32_t qhf[4][4], qlf[4][4];
    {
        uint32_t qb = smu + A_BASE + ABUF + (wid * 16 + (lane & 15)) * AP + (lane >> 4) * 16;
#pragma unroll
        for (int ks = 0; ks < 4; ks++) {
            ldsm4(qhf[ks], qb + ks * 32);
            ldsm4(qlf[ks], qb + ks * 32 + 64 * AP * 2);
        }
    }
    __syncthreads();

    uint4 rv[8], nv[8];
    float rew = 0.f, newv = 0.f;

    auto aload = [&](int kt, uint4* R, float& E) {
#pragma unroll
        for (int i = 0; i < 8; i++) {
            int id = t + i * 256;
            int tile = id >> 9, w = id & 511, row = w >> 3, sg = w & 7;
            const __nv_bfloat16* src;
            size_t g;
            if (tile == 0)      { src = g_kh_hi; g = ((size_t)bh * Sq + kt * 64 + row) * DKh + sg * 8; }
            else if (tile == 1) { src = g_kh_lo; g = ((size_t)bh * Sq + kt * 64 + row) * DKh + sg * 8; }
            else if (tile == 2) { src = g_vt_hi; g = ((size_t)bh * DKh + row) * Sq + kt * 64 + sg * 8; }
            else                { src = g_vt_lo; g = ((size_t)bh * DKh + row) * Sq + kt * 64 + sg * 8; }
            R[i] = *(const uint4*)(src + g);
        }
        if (t < 64) E = g_ew[(size_t)b * Sq + kt * 64 + t];
    };
    auto astore = [&](int kt, const uint4* R, float E) {
        char* dst = smA + A_BASE + (kt & 1) * ABUF;
#pragma unroll
        for (int i = 0; i < 8; i++) {
            int id = t + i * 256;
            int tile = id >> 9, w = id & 511, row = w >> 3, sg = w & 7;
            *(uint4*)(dst + tile * ATS + row * AP + sg * 16) = R[i];
        }
        if (t < 64) *(float*)(smA + (kt & 1) * 256 + t * 4) = E;
    };

    float O[8][4];
#pragma unroll
    for (int j = 0; j < 8; j++)
#pragma unroll
        for (int q = 0; q < 4; q++) O[j][q] = 0.f;
    float m0 = -1e30f, m1 = -1e30f, l0 = 0.f, l1 = 0.f;

    aload(0, rv, rew);

    for (int kt = 0; kt < NKT; kt++) {
        astore(kt, rv, rew);
        __syncthreads();
        if (kt + 1 < NKT) aload(kt + 1, nv, newv);

        uint32_t bK = smu + A_BASE + (kt & 1) * ABUF;

        // ---- S = Q K^T : each K fragment loaded once, used by Qh and Ql ----
        float S[8][4];
#pragma unroll
        for (int j = 0; j < 8; j++)
#pragma unroll
            for (int q = 0; q < 4; q++) S[j][q] = 0.f;

        uint32_t kbh = bK + (lane & 15) * AP + (lane >> 4) * 16;
        uint32_t kbl = kbh + ATS;
#pragma unroll
        for (int ks = 0; ks < 4; ks++) {
#pragma unroll
            for (int j2 = 0; j2 < 4; j2++) {
                uint32_t kh4[4];
                ldsm4(kh4, kbh + j2 * 16 * AP + ks * 32);
                {
                    uint32_t be[2] = {kh4[0], kh4[2]}, bo[2] = {kh4[1], kh4[3]};
                    mma16816(S[2 * j2],     qhf[ks], be);
                    mma16816(S[2 * j2 + 1], qhf[ks], bo);
                    mma16816(S[2 * j2],     qlf[ks], be);
                    mma16816(S[2 * j2 + 1], qlf[ks], bo);
                }
                uint32_t kl4[4];
                ldsm4(kl4, kbl + j2 * 16 * AP + ks * 32);
                {
                    uint32_t be[2] = {kl4[0], kl4[2]}, bo[2] = {kl4[1], kl4[3]};
                    mma16816(S[2 * j2],     qhf[ks], be);
                    mma16816(S[2 * j2 + 1], qhf[ks], bo);
                }
            }
        }

        // ---- softmax (rows lr and lr+8, cols spread over 4 lanes) ----
        const float* ew = (const float*)(smA + (kt & 1) * 256);
        float mt0 = -1e30f, mt1 = -1e30f;
#pragma unroll
        for (int j = 0; j < 8; j++) {
            float2 e = *(const float2*)(ew + 8 * j + 2 * lc);
            S[j][0] *= e.x; S[j][1] *= e.y;
            S[j][2] *= e.x; S[j][3] *= e.y;
            mt0 = fmaxf(mt0, fmaxf(S[j][0], S[j][1]));
            mt1 = fmaxf(mt1, fmaxf(S[j][2], S[j][3]));
        }
        mt0 = fmaxf(mt0, __shfl_xor_sync(0xffffffffu, mt0, 1));
        mt0 = fmaxf(mt0, __shfl_xor_sync(0xffffffffu, mt0, 2));
        mt1 = fmaxf(mt1, __shfl_xor_sync(0xffffffffu, mt1, 1));
        mt1 = fmaxf(mt1, __shfl_xor_sync(0xffffffffu, mt1, 2));
        float mn0 = fmaxf(m0, mt0), mn1 = fmaxf(m1, mt1);
        float al0 = __expf(m0 - mn0), al1 = __expf(m1 - mn1);
        m0 = mn0; m1 = mn1;
        float ps0 = 0.f, ps1 = 0.f;
#pragma unroll
        for (int j = 0; j < 8; j++) {
            S[j][0] = __expf(S[j][0] - mn0); ps0 += S[j][0];
            S[j][1] = __expf(S[j][1] - mn0); ps0 += S[j][1];
            S[j][2] = __expf(S[j][2] - mn1); ps1 += S[j][2];
            S[j][3] = __expf(S[j][3] - mn1); ps1 += S[j][3];
        }
        ps0 += __shfl_xor_sync(0xffffffffu, ps0, 1);
        ps0 += __shfl_xor_sync(0xffffffffu, ps0, 2);
        ps1 += __shfl_xor_sync(0xffffffffu, ps1, 1);
        ps1 += __shfl_xor_sync(0xffffffffu, ps1, 2);
        l0 = l0 * al0 + ps0;
        l1 = l1 * al1 + ps1;
#pragma unroll
        for (int j = 0; j < 8; j++) {
            O[j][0] *= al0; O[j][1] *= al0;
            O[j][2] *= al1; O[j][3] *= al1;
        }

        // ---- P packs (hi/lo), reused directly as mma A operands ----
        uint32_t Ph[8][2], Pl[8][2];
#pragma unroll
        for (int j = 0; j < 8; j++) {
            Ph[j][0] = pk(S[j][0], S[j][1]);
            Ph[j][1] = pk(S[j][2], S[j][3]);
            Pl[j][0] = pk(resid_f(S[j][0]), resid_f(S[j][1]));
            Pl[j][1] = pk(resid_f(S[j][2]), resid_f(S[j][3]));
        }

        // ---- O += P V : each V fragment loaded once, used by Ph and Pl ----
        uint32_t vbh = bK + 2 * ATS + (lane & 15) * AP + (lane >> 4) * 16;
        uint32_t vbl = vbh + ATS;
#pragma unroll
        for (int ks = 0; ks < 4; ks++) {
            uint32_t a4h[4] = {Ph[2 * ks][0], Ph[2 * ks][1], Ph[2 * ks + 1][0], Ph[2 * ks + 1][1]};
            uint32_t a4l[4] = {Pl[2 * ks][0], Pl[2 * ks][1], Pl[2 * ks + 1][0], Pl[2 * ks + 1][1]};
#pragma unroll
            for (int j2 = 0; j2 < 4; j2++) {
                uint32_t vh4[4];
                ldsm4(vh4, vbh + j2 * 16 * AP + ks * 32);
                {
                    uint32_t ve[2] = {vh4[0], vh4[2]}, vo[2] = {vh4[1], vh4[3]};
                    mma16816(O[2 * j2],     a4h, ve);
                    mma16816(O[2 * j2 + 1], a4h, vo);
                    mma16816(O[2 * j2],     a4l, ve);
                    mma16816(O[2 * j2 + 1], a4l, vo);
                }
                uint32_t vl4[4];
                ldsm4(vl4, vbl + j2 * 16 * AP + ks * 32);
                {
                    uint32_t ve[2] = {vl4[0], vl4[2]}, vo[2] = {vl4[1], vl4[3]};
                    mma16816(O[2 * j2],     a4h, ve);
                    mma16816(O[2 * j2 + 1], a4h, vo);
                }
            }
        }

#pragma unroll
        for (int i = 0; i < 8; i++) rv[i] = nv[i];
        rew = newv;
    }

    // ---- finalize + write hi/lo into (B,S,512) ----
    float inv0 = 1.0f / l0, inv1 = 1.0f / l1;
    int row0 = qbase + wid * 16 + lr, row1 = row0 + 8;
    size_t base0 = ((size_t)(b * Sq + row0)) * Dm + (bh & 7) * DKh + 2 * lc;
    size_t base1 = ((size_t)(b * Sq + row1)) * Dm + (bh & 7) * DKh + 2 * lc;
#pragma unroll
    for (int j = 0; j < 8; j++) {
        float v0 = O[j][0] * inv0, v1 = O[j][1] * inv0;
        float v2 = O[j][2] * inv1, v3 = O[j][3] * inv1;
        *(uint32_t*)(g_ao_hi + base0 + 8 * j) = pk(v0, v1);
        *(uint32_t*)(g_ao_lo + base0 + 8 * j) = pk(resid_f(v0), resid_f(v1));
        *(uint32_t*)(g_ao_hi + base1 + 8 * j) = pk(v2, v3);
        *(uint32_t*)(g_ao_lo + base1 + 8 * j) = pk(resid_f(v2), resid_f(v3));
    }
}

// ======================= LayerNorm =======================
__global__ __launch_bounds__(128) void ln_kernel(const float* __restrict__ gamma,
                                                 const float* __restrict__ beta,
                                                 float* __restrict__ out) {
    __shared__ float red[4];
    const int row = blockIdx.x, t = threadIdx.x;
    float4 x = *(const float4*)(g_fc + (size_t)row * Dm + t * 4);
    float s = x.x + x.y + x.z + x.w;
#pragma unroll
    for (int off = 16; off > 0; off >>= 1) s += __shfl_xor_sync(0xffffffffu, s, off);
    if ((t & 31) == 0) red[t >> 5] = s;
    __syncthreads();
    float mu = (red[0] + red[1] + red[2] + red[3]) * (1.0f / Dm);
    float d0 = x.x - mu, d1 = x.y - mu, d2 = x.z - mu, d3 = x.w - mu;
    float sq = d0 * d0 + d1 * d1 + d2 * d2 + d3 * d3;
#pragma unroll
    for (int off = 16; off > 0; off >>= 1) sq += __shfl_xor_sync(0xffffffffu, sq, off);
    __syncthreads();
    if ((t & 31) == 0) red[t >> 5] = sq;
    __syncthreads();
    float var = (red[0] + red[1] + red[2] + red[3]) * (1.0f / Dm);
    float inv = rsqrtf(var + 1e-5f);
    int c = t * 4;
    float4 g = *(const float4*)(gamma + c);
    float4 be = *(const float4*)(beta + c);
    *(float4*)(out + (size_t)row * Dm + c) =
        make_float4(d0 * inv * g.x + be.x, d1 * inv * g.y + be.y,
                    d2 * inv * g.z + be.z, d3 * inv * g.w + be.w);
}

// ======================= launch =======================
extern "C" void kernel_launch(void* const* d_in, const int* in_sizes, int n_in,
                              void* d_out, int out_size) {
    const float* Q   = (const float*)d_in[0];
    const float* K   = (const float*)d_in[1];
    const float* V   = (const float*)d_in[2];
    const float* ent = (const float*)d_in[3];
    const float* Wq  = (const float*)d_in[4];
    const float* bq  = (const float*)d_in[5];
    const float* Wk  = (const float*)d_in[6];
    const float* bk  = (const float*)d_in[7];
    const float* Wv  = (const float*)d_in[8];
    const float* bv  = (const float*)d_in[9];
    const float* Wfc = (const float*)d_in[10];
    const float* bfc = (const float*)d_in[11];
    const float* We  = (const float*)d_in[12];
    const float* gam = (const float*)d_in[13];
    const float* bet = (const float*)d_in[14];
    float* out = (float*)d_out;

    cudaFuncSetAttribute(attn_tc, cudaFuncAttributeMaxDynamicSharedMemorySize, AT_SMEM);
    cudaFuncSetAttribute(gemm_tc, cudaFuncAttributeMaxDynamicSharedMemorySize, GSMEM);

    ew_kernel<<<(Bz * Sq) / 256, 256>>>(We, ent);
    split_kernel<<<4096, 256>>>(Q, 0, Mrows * Dm / 4);
    split_kernel<<<4096, 256>>>(K, 1, Mrows * Dm / 4);
    split_kernel<<<4096, 256>>>(V, 2, Mrows * Dm / 4);
    split_kernel<<<256, 256>>>(Wq, 3, Dm * Dm / 4);
    split_kernel<<<256, 256>>>(Wk, 4, Dm * Dm / 4);
    split_kernel<<<256, 256>>>(Wv, 5, Dm * Dm / 4);
    split_kernel<<<256, 256>>>(Wfc, 6, Dm * Dm / 4);

    dim3 gg(Dm / 128, Mrows / 128);   // (4, 64)
    gemm_tc<<<gg, 256, GSMEM>>>(bq, nullptr, 0);
    gemm_tc<<<gg, 256, GSMEM>>>(bk, nullptr, 1);
    gemm_tc<<<gg, 256, GSMEM>>>(bv, nullptr, 2);

    attn_tc<<<dim3(Sq / 128, Bz * Hh), 256, AT_SMEM>>>();

    gemm_tc<<<gg, 256, GSMEM>>>(bfc, Q, 3);
    ln_kernel<<<Mrows, 128>>>(gam, bet, out);
}

// round 12
// speedup vs baseline: 2.6863x; 1.0794x over previous
#include <cuda_runtime.h>
#include <cuda_bf16.h>
#include <cstdint>
#include <cstddef>

#define Bz 4
#define Sq 2048
#define Dm 512
#define Hh 8
#define DKh 64
#define Mrows (Bz*Sq)   // 8192

// ======================= scratch (__device__ globals) =======================
__device__ __nv_bfloat16 g_wq_hi[Dm*Dm], g_wq_lo[Dm*Dm];
__device__ __nv_bfloat16 g_wk_hi[Dm*Dm], g_wk_lo[Dm*Dm];
__device__ __nv_bfloat16 g_wv_hi[Dm*Dm], g_wv_lo[Dm*Dm];
__device__ __nv_bfloat16 g_wf_hi[Dm*Dm], g_wf_lo[Dm*Dm];
__device__ __nv_bfloat16 g_qh_hi[Mrows*Dm], g_qh_lo[Mrows*Dm];   // (B,H,S,64)
__device__ __nv_bfloat16 g_kh_hi[Mrows*Dm], g_kh_lo[Mrows*Dm];   // (B,H,S,64)
__device__ __nv_bfloat16 g_vt_hi[Mrows*Dm];                      // (B,H,64,S)
__device__ float g_ao[Mrows*Dm];                                 // attention out fp32 (B,S,D)
__device__ float g_fc[Mrows*Dm];
__device__ float g_ew[Bz*Sq];

// ======================= helpers =======================
__device__ __forceinline__ uint32_t smem_u32(const void* p) {
    uint32_t a;
    asm("{ .reg .u64 t; cvta.to.shared.u64 t, %1; cvt.u32.u64 %0, t; }" : "=r"(a) : "l"(p));
    return a;
}
__device__ __forceinline__ void ldsm4(uint32_t* r, uint32_t addr) {
    asm volatile("ldmatrix.sync.aligned.m8n8.x4.shared.b16 {%0,%1,%2,%3}, [%4];"
        : "=r"(r[0]), "=r"(r[1]), "=r"(r[2]), "=r"(r[3]) : "r"(addr));
}
__device__ __forceinline__ void mma16816(float* d, const uint32_t* a, const uint32_t* b) {
    asm volatile("mma.sync.aligned.m16n8k16.row.col.f32.bf16.bf16.f32 "
        "{%0,%1,%2,%3}, {%4,%5,%6,%7}, {%8,%9}, {%0,%1,%2,%3};"
        : "+f"(d[0]), "+f"(d[1]), "+f"(d[2]), "+f"(d[3])
        : "r"(a[0]), "r"(a[1]), "r"(a[2]), "r"(a[3]), "r"(b[0]), "r"(b[1]));
}
// pack two floats into bf16x2 (v0 -> low half)
__device__ __forceinline__ uint32_t pk(float v0, float v1) {
    uint32_t r;
    asm("cvt.rn.bf16x2.f32 %0, %1, %2;" : "=r"(r) : "f"(v1), "f"(v0));
    return r;
}
__device__ __forceinline__ float resid_f(float v) {
    return v - __bfloat162float(__float2bfloat16(v));
}
__device__ __forceinline__ uint32_t pack_bf2(__nv_bfloat16 a, __nv_bfloat16 b) {
    __nv_bfloat162 v; v.x = a; v.y = b;
    return *reinterpret_cast<uint32_t*>(&v);
}

// ======================= K0: entropy weights =======================
__global__ void ew_kernel(const float* __restrict__ We, const float* __restrict__ ent) {
    int i = blockIdx.x * 256 + threadIdx.x;
    int s = i & (Sq - 1);
    g_ew[i] = 8.0f * __expf(We[s] * ent[i]);
}

// ======================= split fp32 -> bf16 hi/lo (weights only) =======================
__global__ void split_kernel(const float* __restrict__ src, int which, int n4) {
    int i = blockIdx.x * 256 + threadIdx.x;
    if (i >= n4) return;
    __nv_bfloat16 *hi, *lo;
    switch (which) {
        case 3: hi = g_wq_hi; lo = g_wq_lo; break;
        case 4: hi = g_wk_hi; lo = g_wk_lo; break;
        case 5: hi = g_wv_hi; lo = g_wv_lo; break;
        default: hi = g_wf_hi; lo = g_wf_lo; break;
    }
    float4 v = ((const float4*)src)[i];
    __nv_bfloat16 h0 = __float2bfloat16(v.x), h1 = __float2bfloat16(v.y);
    __nv_bfloat16 h2 = __float2bfloat16(v.z), h3 = __float2bfloat16(v.w);
    __nv_bfloat16 l0 = __float2bfloat16(v.x - __bfloat162float(h0));
    __nv_bfloat16 l1 = __float2bfloat16(v.y - __bfloat162float(h1));
    __nv_bfloat16 l2 = __float2bfloat16(v.z - __bfloat162float(h2));
    __nv_bfloat16 l3 = __float2bfloat16(v.w - __bfloat162float(h3));
    ((uint2*)hi)[i] = make_uint2(pack_bf2(h0, h1), pack_bf2(h2, h3));
    ((uint2*)lo)[i] = make_uint2(pack_bf2(l0, l1), pack_bf2(l2, l3));
}

// ======================= GEMM: C[8192,512] = A * W^T (fused 3-pass hi/lo) =======================
// CTA 128x128, BK=32, 8 warps (4x2), warp tile 32x64.
// A read as fp32 (inputs or g_ao), split to bf16 hi/lo INLINE (no input split kernels).
#define GP 80
#define GTILE 10240       // 128 rows x 80B
#define GBUF  (4*GTILE)   // tiles {Ah, Al, Wh, Wl}
#define GSMEM (2*GBUF)    // 81920

__global__ __launch_bounds__(256, 1) void gemm_tc(const float* __restrict__ Aext,
                                                  const float* __restrict__ bias,
                                                  const float* __restrict__ resid,
                                                  int mode) {
    extern __shared__ __align__(16) char gsm[];
    const int t = threadIdx.x, lane = t & 31, wid = t >> 5;
    const int wm = wid & 3, wn = wid >> 2;
    const int lr = lane >> 2, lc = lane & 3;
    const int mbase = blockIdx.y * 128, nbase = blockIdx.x * 128;

    const float* Ap = (mode == 3) ? g_ao : Aext;
    const __nv_bfloat16 *Wh, *Wl;
    switch (mode) {
        case 0: Wh = g_wq_hi; Wl = g_wq_lo; break;
        case 1: Wh = g_wk_hi; Wl = g_wk_lo; break;
        case 2: Wh = g_wv_hi; Wl = g_wv_lo; break;
        default: Wh = g_wf_hi; Wl = g_wf_lo; break;
    }

    float acc[2][8][4];
#pragma unroll
    for (int i = 0; i < 2; i++)
#pragma unroll
        for (int j = 0; j < 8; j++)
#pragma unroll
            for (int q = 0; q < 4; q++) acc[i][j][q] = 0.f;

    uint4 rr[8], nn[8];   // [0..3]: A fp32, [4..7]: Wh/Wl bf16

    auto gload = [&](int c, uint4* R) {
        int kk = c * 32;
#pragma unroll
        for (int i = 0; i < 4; i++) {       // A tile fp32: 128 rows x 32 floats
            int id = t + i * 256;
            int row = id >> 3, sg = id & 7;
            R[i] = *(const uint4*)(Ap + (size_t)(mbase + row) * Dm + kk + sg * 4);
        }
#pragma unroll
        for (int i = 0; i < 4; i++) {       // Wh, Wl tiles bf16
            int id = t + i * 256;
            int tile = id >> 9, w = id & 511, row = w >> 2, sg = w & 3;
            const __nv_bfloat16* src = (tile == 0) ? Wh : Wl;
            R[4 + i] = *(const uint4*)(src + (size_t)(nbase + row) * Dm + kk + sg * 8);
        }
    };
    auto gstore = [&](int c, const uint4* R) {
        char* buf = gsm + (c & 1) * GBUF;
#pragma unroll
        for (int i = 0; i < 4; i++) {       // split A fp32 -> Ah/Al
            int id = t + i * 256;
            int row = id >> 3, sg = id & 7;
            float4 v = *(const float4*)&R[i];
            uint2 hi = make_uint2(pk(v.x, v.y), pk(v.z, v.w));
            uint2 lo = make_uint2(pk(resid_f(v.x), resid_f(v.y)), pk(resid_f(v.z), resid_f(v.w)));
            *(uint2*)(buf + row * GP + sg * 8) = hi;
            *(uint2*)(buf + GTILE + row * GP + sg * 8) = lo;
        }
#pragma unroll
        for (int i = 0; i < 4; i++) {
            int id = t + i * 256;
            int tile = id >> 9, w = id & 511, row = w >> 2, sg = w & 3;
            *(uint4*)(buf + (2 + tile) * GTILE + row * GP + sg * 16) = R[4 + i];
        }
    };

    gload(0, rr);

    for (int c = 0; c < 16; c++) {
        gstore(c, rr);
        __syncthreads();
        if (c + 1 < 16) gload(c + 1, nn);

        uint32_t bufu = smem_u32(gsm + (c & 1) * GBUF);
#pragma unroll
        for (int ks = 0; ks < 2; ks++) {
            uint32_t afh[2][4], afl[2][4];
            uint32_t arow = bufu + (wm * 32 + (lane & 15)) * GP + ks * 32 + (lane >> 4) * 16;
            ldsm4(afh[0], arow);
            ldsm4(afh[1], arow + 16 * GP);
            ldsm4(afl[0], arow + GTILE);
            ldsm4(afl[1], arow + GTILE + 16 * GP);
            uint32_t brow = bufu + 2 * GTILE + (wn * 64 + (lane & 15)) * GP + ks * 32 + (lane >> 4) * 16;
#pragma unroll
            for (int j2 = 0; j2 < 4; j2++) {
                uint32_t wh4[4];
                ldsm4(wh4, brow + j2 * 16 * GP);
                {
                    uint32_t be[2] = {wh4[0], wh4[2]}, bo[2] = {wh4[1], wh4[3]};
#pragma unroll
                    for (int i = 0; i < 2; i++) {
                        mma16816(acc[i][2 * j2],     afh[i], be);
                        mma16816(acc[i][2 * j2 + 1], afh[i], bo);
                        mma16816(acc[i][2 * j2],     afl[i], be);
                        mma16816(acc[i][2 * j2 + 1], afl[i], bo);
                    }
                }
                uint32_t wl4[4];
                ldsm4(wl4, brow + GTILE + j2 * 16 * GP);
                {
                    uint32_t be[2] = {wl4[0], wl4[2]}, bo[2] = {wl4[1], wl4[3]};
#pragma unroll
                    for (int i = 0; i < 2; i++) {
                        mma16816(acc[i][2 * j2],     afh[i], be);
                        mma16816(acc[i][2 * j2 + 1], afh[i], bo);
                    }
                }
            }
        }
#pragma unroll
        for (int i = 0; i < 8; i++) rr[i] = nn[i];
    }

    // epilogue
#pragma unroll
    for (int i = 0; i < 2; i++) {
        int m0 = mbase + wm * 32 + i * 16 + lr;
        int m1 = m0 + 8;
#pragma unroll
        for (int j = 0; j < 8; j++) {
            int n = nbase + wn * 64 + 8 * j + 2 * lc;
            float b0 = bias[n], b1 = bias[n + 1];
            float v0 = acc[i][j][0] + b0, v1 = acc[i][j][1] + b1;   // row m0
            float v2 = acc[i][j][2] + b0, v3 = acc[i][j][3] + b1;   // row m1
            if (mode == 3) {
                size_t o0 = (size_t)m0 * Dm + n, o1 = (size_t)m1 * Dm + n;
                float2 r0 = *(const float2*)(resid + o0);
                float2 r1 = *(const float2*)(resid + o1);
                *(float2*)(g_fc + o0) = make_float2(v0 + r0.x, v1 + r0.y);
                *(float2*)(g_fc + o1) = make_float2(v2 + r1.x, v3 + r1.y);
            } else if (mode == 2) {
                int h = n >> 6, dl = n & 63;
                int b0_ = m0 >> 11, s0 = m0 & (Sq - 1);
                int b1_ = m1 >> 11, s1 = m1 & (Sq - 1);
                size_t p00 = ((size_t)(b0_ * Hh + h) * DKh + dl) * Sq + s0;
                size_t p10 = ((size_t)(b1_ * Hh + h) * DKh + dl) * Sq + s1;
                g_vt_hi[p00] = __float2bfloat16(v0); g_vt_hi[p00 + Sq] = __float2bfloat16(v1);
                g_vt_hi[p10] = __float2bfloat16(v2); g_vt_hi[p10 + Sq] = __float2bfloat16(v3);
            } else {
                int h = n >> 6, dl = n & 63;
                int b0_ = m0 >> 11, s0 = m0 & (Sq - 1);
                int b1_ = m1 >> 11, s1 = m1 & (Sq - 1);
                size_t o0 = ((size_t)(b0_ * Hh + h) * Sq + s0) * DKh + dl;
                size_t o1 = ((size_t)(b1_ * Hh + h) * Sq + s1) * DKh + dl;
                __nv_bfloat16* oh = (mode == 0) ? g_qh_hi : g_kh_hi;
                __nv_bfloat16* ol = (mode == 0) ? g_qh_lo : g_kh_lo;
                *(uint32_t*)(oh + o0) = pk(v0, v1);
                *(uint32_t*)(ol + o0) = pk(resid_f(v0), resid_f(v1));
                *(uint32_t*)(oh + o1) = pk(v2, v3);
                *(uint32_t*)(ol + o1) = pk(resid_f(v2), resid_f(v3));
            }
        }
    }
}

// ======================= flash attention =======================
// grid (16, 32), 256 thr (8 warps). Tq=128 (warp: 16 rows), Tk=64, dk=64.
// S: 3-pass (QhKh + QhKl + QlKh). PV: 2-pass (PhVh + PlVh) — V bf16 only.
// Q staging: QTS = 128 rows x 144B per half; region overlaps k-tile buffer 1
// (legal: Q is consumed into registers before buffer 1 is first written).
#define AP 144
#define ATS 9216          // one k-tile: 64*144
#define ABUF (3*ATS)      // {Kh, Kl, Vh} = 27648
#define QTS  18432        // one Q half: 128*144
#define A_BASE 512
#define AT_SMEM (A_BASE + ABUF + 2*QTS)   // 65024
#define NKT (Sq/64)       // 32

__global__ __launch_bounds__(256, 1) void attn_tc() {
    extern __shared__ char smA[];
    const uint32_t smu = smem_u32(smA);
    const int t = threadIdx.x, lane = t & 31, wid = t >> 5;
    const int lr = lane >> 2, lc = lane & 3;
    const int bh = blockIdx.y, b = bh >> 3;
    const int qbase = blockIdx.x * 128;

    // ---- stage Q (hi/lo) beyond buffer 0, load into registers ----
    {
        char* qdst = smA + A_BASE + ABUF;
#pragma unroll
        for (int i = 0; i < 8; i++) {
            int id = t + i * 256;
            int half = id >> 10, w = id & 1023, row = w >> 3, sg = w & 7;
            const __nv_bfloat16* src = half ? g_qh_lo : g_qh_hi;
            *(uint4*)(qdst + half * QTS + row * AP + sg * 16) =
                *(const uint4*)(src + ((size_t)bh * Sq + qbase + row) * DKh + sg * 8);
        }
    }
    __syncthreads();

    uint32_t qhf[4][4], qlf[4][4];
    {
        uint32_t qb = smu + A_BASE + ABUF + (wid * 16 + (lane & 15)) * AP + (lane >> 4) * 16;
#pragma unroll
        for (int ks = 0; ks < 4; ks++) {
            ldsm4(qhf[ks], qb + ks * 32);
            ldsm4(qlf[ks], qb + ks * 32 + QTS);
        }
    }
    __syncthreads();

    uint4 rv[6], nv[6];
    float rew = 0.f, newv = 0.f;

    auto aload = [&](int kt, uint4* R, float& E) {
#pragma unroll
        for (int i = 0; i < 6; i++) {
            int id = t + i * 256;
            int tile = id >> 9, w = id & 511, row = w >> 3, sg = w & 7;
            const __nv_bfloat16* src;
            size_t g;
            if (tile == 0)      { src = g_kh_hi; g = ((size_t)bh * Sq + kt * 64 + row) * DKh + sg * 8; }
            else if (tile == 1) { src = g_kh_lo; g = ((size_t)bh * Sq + kt * 64 + row) * DKh + sg * 8; }
            else                { src = g_vt_hi; g = ((size_t)bh * DKh + row) * Sq + kt * 64 + sg * 8; }
            R[i] = *(const uint4*)(src + g);
        }
        if (t < 64) E = g_ew[(size_t)b * Sq + kt * 64 + t];
    };
    auto astore = [&](int kt, const uint4* R, float E) {
        char* dst = smA + A_BASE + (kt & 1) * ABUF;
#pragma unroll
        for (int i = 0; i < 6; i++) {
            int id = t + i * 256;
            int tile = id >> 9, w = id & 511, row = w >> 3, sg = w & 7;
            *(uint4*)(dst + tile * ATS + row * AP + sg * 16) = R[i];
        }
        if (t < 64) *(float*)(smA + (kt & 1) * 256 + t * 4) = E;
    };

    float O[8][4];
#pragma unroll
    for (int j = 0; j < 8; j++)
#pragma unroll
        for (int q = 0; q < 4; q++) O[j][q] = 0.f;
    float m0 = -1e30f, m1 = -1e30f, l0 = 0.f, l1 = 0.f;

    aload(0, rv, rew);

    for (int kt = 0; kt < NKT; kt++) {
        astore(kt, rv, rew);
        __syncthreads();
        if (kt + 1 < NKT) aload(kt + 1, nv, newv);

        uint32_t bK = smu + A_BASE + (kt & 1) * ABUF;

        // ---- S = Q K^T : each K fragment loaded once, used by Qh and Ql ----
        float S[8][4];
#pragma unroll
        for (int j = 0; j < 8; j++)
#pragma unroll
            for (int q = 0; q < 4; q++) S[j][q] = 0.f;

        uint32_t kbh = bK + (lane & 15) * AP + (lane >> 4) * 16;
        uint32_t kbl = kbh + ATS;
#pragma unroll
        for (int ks = 0; ks < 4; ks++) {
#pragma unroll
            for (int j2 = 0; j2 < 4; j2++) {
                uint32_t kh4[4];
                ldsm4(kh4, kbh + j2 * 16 * AP + ks * 32);
                {
                    uint32_t be[2] = {kh4[0], kh4[2]}, bo[2] = {kh4[1], kh4[3]};
                    mma16816(S[2 * j2],     qhf[ks], be);
                    mma16816(S[2 * j2 + 1], qhf[ks], bo);
                    mma16816(S[2 * j2],     qlf[ks], be);
                    mma16816(S[2 * j2 + 1], qlf[ks], bo);
                }
                uint32_t kl4[4];
                ldsm4(kl4, kbl + j2 * 16 * AP + ks * 32);
                {
                    uint32_t be[2] = {kl4[0], kl4[2]}, bo[2] = {kl4[1], kl4[3]};
                    mma16816(S[2 * j2],     qhf[ks], be);
                    mma16816(S[2 * j2 + 1], qhf[ks], bo);
                }
            }
        }

        // ---- softmax (rows lr and lr+8, cols spread over 4 lanes) ----
        const float* ew = (const float*)(smA + (kt & 1) * 256);
        float mt0 = -1e30f, mt1 = -1e30f;
#pragma unroll
        for (int j = 0; j < 8; j++) {
            float2 e = *(const float2*)(ew + 8 * j + 2 * lc);
            S[j][0] *= e.x; S[j][1] *= e.y;
            S[j][2] *= e.x; S[j][3] *= e.y;
            mt0 = fmaxf(mt0, fmaxf(S[j][0], S[j][1]));
            mt1 = fmaxf(mt1, fmaxf(S[j][2], S[j][3]));
        }
        mt0 = fmaxf(mt0, __shfl_xor_sync(0xffffffffu, mt0, 1));
        mt0 = fmaxf(mt0, __shfl_xor_sync(0xffffffffu, mt0, 2));
        mt1 = fmaxf(mt1, __shfl_xor_sync(0xffffffffu, mt1, 1));
        mt1 = fmaxf(mt1, __shfl_xor_sync(0xffffffffu, mt1, 2));
        float mn0 = fmaxf(m0, mt0), mn1 = fmaxf(m1, mt1);
        float al0 = __expf(m0 - mn0), al1 = __expf(m1 - mn1);
        m0 = mn0; m1 = mn1;
        float ps0 = 0.f, ps1 = 0.f;
#pragma unroll
        for (int j = 0; j < 8; j++) {
            S[j][0] = __expf(S[j][0] - mn0); ps0 += S[j][0];
            S[j][1] = __expf(S[j][1] - mn0); ps0 += S[j][1];
            S[j][2] = __expf(S[j][2] - mn1); ps1 += S[j][2];
            S[j][3] = __expf(S[j][3] - mn1); ps1 += S[j][3];
        }
        ps0 += __shfl_xor_sync(0xffffffffu, ps0, 1);
        ps0 += __shfl_xor_sync(0xffffffffu, ps0, 2);
        ps1 += __shfl_xor_sync(0xffffffffu, ps1, 1);
        ps1 += __shfl_xor_sync(0xffffffffu, ps1, 2);
        l0 = l0 * al0 + ps0;
        l1 = l1 * al1 + ps1;
#pragma unroll
        for (int j = 0; j < 8; j++) {
            O[j][0] *= al0; O[j][1] *= al0;
            O[j][2] *= al1; O[j][3] *= al1;
        }

        // ---- P packs (hi/lo), reused directly as mma A operands ----
        uint32_t Ph[8][2], Pl[8][2];
#pragma unroll
        for (int j = 0; j < 8; j++) {
            Ph[j][0] = pk(S[j][0], S[j][1]);
            Ph[j][1] = pk(S[j][2], S[j][3]);
            Pl[j][0] = pk(resid_f(S[j][0]), resid_f(S[j][1]));
            Pl[j][1] = pk(resid_f(S[j][2]), resid_f(S[j][3]));
        }

        // ---- O += P V : 2-pass, each V fragment loaded once (Ph and Pl) ----
        uint32_t vbh = bK + 2 * ATS + (lane & 15) * AP + (lane >> 4) * 16;
#pragma unroll
        for (int ks = 0; ks < 4; ks++) {
            uint32_t a4h[4] = {Ph[2 * ks][0], Ph[2 * ks][1], Ph[2 * ks + 1][0], Ph[2 * ks + 1][1]};
            uint32_t a4l[4] = {Pl[2 * ks][0], Pl[2 * ks][1], Pl[2 * ks + 1][0], Pl[2 * ks + 1][1]};
#pragma unroll
            for (int j2 = 0; j2 < 4; j2++) {
                uint32_t vh4[4];
                ldsm4(vh4, vbh + j2 * 16 * AP + ks * 32);
                uint32_t ve[2] = {vh4[0], vh4[2]}, vo[2] = {vh4[1], vh4[3]};
                mma16816(O[2 * j2],     a4h, ve);
                mma16816(O[2 * j2 + 1], a4h, vo);
                mma16816(O[2 * j2],     a4l, ve);
                mma16816(O[2 * j2 + 1], a4l, vo);
            }
        }

#pragma unroll
        for (int i = 0; i < 6; i++) rv[i] = nv[i];
        rew = newv;
    }

    // ---- finalize + write fp32 into g_ao (B,S,512) ----
    float inv0 = 1.0f / l0, inv1 = 1.0f / l1;
    int row0 = qbase + wid * 16 + lr, row1 = row0 + 8;
    size_t base0 = ((size_t)(b * Sq + row0)) * Dm + (bh & 7) * DKh + 2 * lc;
    size_t base1 = ((size_t)(b * Sq + row1)) * Dm + (bh & 7) * DKh + 2 * lc;
#pragma unroll
    for (int j = 0; j < 8; j++) {
        *(float2*)(g_ao + base0 + 8 * j) = make_float2(O[j][0] * inv0, O[j][1] * inv0);
        *(float2*)(g_ao + base1 + 8 * j) = make_float2(O[j][2] * inv1, O[j][3] * inv1);
    }
}

// ======================= LayerNorm =======================
__global__ __launch_bounds__(128) void ln_kernel(const float* __restrict__ gamma,
                                                 const float* __restrict__ beta,
                                                 float* __restrict__ out) {
    __shared__ float red[4];
    const int row = blockIdx.x, t = threadIdx.x;
    float4 x = *(const float4*)(g_fc + (size_t)row * Dm + t * 4);
    float s = x.x + x.y + x.z + x.w;
#pragma unroll
    for (int off = 16; off > 0; off >>= 1) s += __shfl_xor_sync(0xffffffffu, s, off);
    if ((t & 31) == 0) red[t >> 5] = s;
    __syncthreads();
    float mu = (red[0] + red[1] + red[2] + red[3]) * (1.0f / Dm);
    float d0 = x.x - mu, d1 = x.y - mu, d2 = x.z - mu, d3 = x.w - mu;
    float sq = d0 * d0 + d1 * d1 + d2 * d2 + d3 * d3;
#pragma unroll
    for (int off = 16; off > 0; off >>= 1) sq += __shfl_xor_sync(0xffffffffu, sq, off);
    __syncthreads();
    if ((t & 31) == 0) red[t >> 5] = sq;
    __syncthreads();
    float var = (red[0] + red[1] + red[2] + red[3]) * (1.0f / Dm);
    float inv = rsqrtf(var + 1e-5f);
    int c = t * 4;
    float4 g = *(const float4*)(gamma + c);
    float4 be = *(const float4*)(beta + c);
    *(float4*)(out + (size_t)row * Dm + c) =
        make_float4(d0 * inv * g.x + be.x, d1 * inv * g.y + be.y,
                    d2 * inv * g.z + be.z, d3 * inv * g.w + be.w);
}

// ======================= launch =======================
extern "C" void kernel_launch(void* const* d_in, const int* in_sizes, int n_in,
                              void* d_out, int out_size) {
    const float* Q   = (const float*)d_in[0];
    const float* K   = (const float*)d_in[1];
    const float* V   = (const float*)d_in[2];
    const float* ent = (const float*)d_in[3];
    const float* Wq  = (const float*)d_in[4];
    const float* bq  = (const float*)d_in[5];
    const float* Wk  = (const float*)d_in[6];
    const float* bk  = (const float*)d_in[7];
    const float* Wv  = (const float*)d_in[8];
    const float* bv  = (const float*)d_in[9];
    const float* Wfc = (const float*)d_in[10];
    const float* bfc = (const float*)d_in[11];
    const float* We  = (const float*)d_in[12];
    const float* gam = (const float*)d_in[13];
    const float* bet = (const float*)d_in[14];
    float* out = (float*)d_out;

    cudaFuncSetAttribute(attn_tc, cudaFuncAttributeMaxDynamicSharedMemorySize, AT_SMEM);
    cudaFuncSetAttribute(gemm_tc, cudaFuncAttributeMaxDynamicSharedMemorySize, GSMEM);

    ew_kernel<<<(Bz * Sq) / 256, 256>>>(We, ent);
    split_kernel<<<256, 256>>>(Wq, 3, Dm * Dm / 4);
    split_kernel<<<256, 256>>>(Wk, 4, Dm * Dm / 4);
    split_kernel<<<256, 256>>>(Wv, 5, Dm * Dm / 4);
    split_kernel<<<256, 256>>>(Wfc, 6, Dm * Dm / 4);

    dim3 gg(Dm / 128, Mrows / 128);   // (4, 64)
    gemm_tc<<<gg, 256, GSMEM>>>(Q, bq, nullptr, 0);
    gemm_tc<<<gg, 256, GSMEM>>>(K, bk, nullptr, 1);
    gemm_tc<<<gg, 256, GSMEM>>>(V, bv, nullptr, 2);

    attn_tc<<<dim3(Sq / 128, Bz * Hh), 256, AT_SMEM>>>();

    gemm_tc<<<gg, 256, GSMEM>>>(nullptr, bfc, Q, 3);
    ln_kernel<<<Mrows, 128>>>(gam, bet, out);
}

// round 13
// speedup vs baseline: 2.7221x; 1.0133x over previous
#include <cuda_runtime.h>
#include <cuda_bf16.h>
#include <cstdint>
#include <cstddef>

#define Bz 4
#define Sq 2048
#define Dm 512
#define Hh 8
#define DKh 64
#define Mrows (Bz*Sq)   // 8192

// ======================= scratch (__device__ globals) =======================
__device__ __nv_bfloat16 g_wq_hi[Dm*Dm], g_wq_lo[Dm*Dm];
__device__ __nv_bfloat16 g_wk_hi[Dm*Dm], g_wk_lo[Dm*Dm];
__device__ __nv_bfloat16 g_wv_hi[Dm*Dm], g_wv_lo[Dm*Dm];
__device__ __nv_bfloat16 g_wf_hi[Dm*Dm], g_wf_lo[Dm*Dm];
__device__ __nv_bfloat16 g_qh_hi[Mrows*Dm], g_qh_lo[Mrows*Dm];   // (B,H,S,64)
__device__ __nv_bfloat16 g_kh_hi[Mrows*Dm], g_kh_lo[Mrows*Dm];   // (B,H,S,64)
__device__ __nv_bfloat16 g_vt_hi[Mrows*Dm];                      // (B,H,64,S)
__device__ float g_ao[Mrows*Dm];                                 // attention out fp32 (B,S,D)
__device__ float g_fc[Mrows*Dm];
__device__ float g_ew[Bz*Sq];

// ======================= helpers =======================
__device__ __forceinline__ uint32_t smem_u32(const void* p) {
    uint32_t a;
    asm("{ .reg .u64 t; cvta.to.shared.u64 t, %1; cvt.u32.u64 %0, t; }" : "=r"(a) : "l"(p));
    return a;
}
__device__ __forceinline__ void ldsm4(uint32_t* r, uint32_t addr) {
    asm volatile("ldmatrix.sync.aligned.m8n8.x4.shared.b16 {%0,%1,%2,%3}, [%4];"
        : "=r"(r[0]), "=r"(r[1]), "=r"(r[2]), "=r"(r[3]) : "r"(addr));
}
__device__ __forceinline__ void mma16816(float* d, const uint32_t* a, const uint32_t* b) {
    asm volatile("mma.sync.aligned.m16n8k16.row.col.f32.bf16.bf16.f32 "
        "{%0,%1,%2,%3}, {%4,%5,%6,%7}, {%8,%9}, {%0,%1,%2,%3};"
        : "+f"(d[0]), "+f"(d[1]), "+f"(d[2]), "+f"(d[3])
        : "r"(a[0]), "r"(a[1]), "r"(a[2]), "r"(a[3]), "r"(b[0]), "r"(b[1]));
}
// pack two floats into bf16x2 (v0 -> low half)
__device__ __forceinline__ uint32_t pk(float v0, float v1) {
    uint32_t r;
    asm("cvt.rn.bf16x2.f32 %0, %1, %2;" : "=r"(r) : "f"(v1), "f"(v0));
    return r;
}
__device__ __forceinline__ float resid_f(float v) {
    return v - __bfloat162float(__float2bfloat16(v));
}
__device__ __forceinline__ uint32_t pack_bf2(__nv_bfloat16 a, __nv_bfloat16 b) {
    __nv_bfloat162 v; v.x = a; v.y = b;
    return *reinterpret_cast<uint32_t*>(&v);
}

// ======================= K0: entropy weights =======================
__global__ void ew_kernel(const float* __restrict__ We, const float* __restrict__ ent) {
    int i = blockIdx.x * 256 + threadIdx.x;
    int s = i & (Sq - 1);
    g_ew[i] = 8.0f * __expf(We[s] * ent[i]);
}

// ======================= fused weight splits: fp32 -> bf16 hi/lo =======================
// grid (256, 4): blockIdx.y selects {Wq, Wk, Wv, Wfc}
__global__ void wsplit_kernel(const float* __restrict__ Wq, const float* __restrict__ Wk,
                              const float* __restrict__ Wv, const float* __restrict__ Wfc) {
    int which = blockIdx.y;
    const float* src;
    __nv_bfloat16 *hi, *lo;
    switch (which) {
        case 0: src = Wq;  hi = g_wq_hi; lo = g_wq_lo; break;
        case 1: src = Wk;  hi = g_wk_hi; lo = g_wk_lo; break;
        case 2: src = Wv;  hi = g_wv_hi; lo = g_wv_lo; break;
        default: src = Wfc; hi = g_wf_hi; lo = g_wf_lo; break;
    }
    int i = blockIdx.x * 256 + threadIdx.x;   // i < Dm*Dm/4 = 65536
    float4 v = ((const float4*)src)[i];
    __nv_bfloat16 h0 = __float2bfloat16(v.x), h1 = __float2bfloat16(v.y);
    __nv_bfloat16 h2 = __float2bfloat16(v.z), h3 = __float2bfloat16(v.w);
    __nv_bfloat16 l0 = __float2bfloat16(v.x - __bfloat162float(h0));
    __nv_bfloat16 l1 = __float2bfloat16(v.y - __bfloat162float(h1));
    __nv_bfloat16 l2 = __float2bfloat16(v.z - __bfloat162float(h2));
    __nv_bfloat16 l3 = __float2bfloat16(v.w - __bfloat162float(h3));
    ((uint2*)hi)[i] = make_uint2(pack_bf2(h0, h1), pack_bf2(h2, h3));
    ((uint2*)lo)[i] = make_uint2(pack_bf2(l0, l1), pack_bf2(l2, l3));
}

// ======================= GEMM: C[8192,512] = A * W^T (fused 3-pass hi/lo) =======================
// CTA 128x128, BK=32, 8 warps (4x2), warp tile 32x64.
// A read as fp32 (inputs or g_ao), split to bf16 hi/lo INLINE.
// Inner loop software-pipelined: Wh fragments double-buffered, Wl issued early.
#define GP 80
#define GTILE 10240       // 128 rows x 80B
#define GBUF  (4*GTILE)   // tiles {Ah, Al, Wh, Wl}
#define GSMEM (2*GBUF)    // 81920

__global__ __launch_bounds__(256, 1) void gemm_tc(const float* __restrict__ Aext,
                                                  const float* __restrict__ bias,
                                                  const float* __restrict__ resid,
                                                  int mode) {
    extern __shared__ __align__(16) char gsm[];
    const int t = threadIdx.x, lane = t & 31, wid = t >> 5;
    const int wm = wid & 3, wn = wid >> 2;
    const int lr = lane >> 2, lc = lane & 3;
    const int mbase = blockIdx.y * 128, nbase = blockIdx.x * 128;

    const float* Ap = (mode == 3) ? g_ao : Aext;
    const __nv_bfloat16 *Wh, *Wl;
    switch (mode) {
        case 0: Wh = g_wq_hi; Wl = g_wq_lo; break;
        case 1: Wh = g_wk_hi; Wl = g_wk_lo; break;
        case 2: Wh = g_wv_hi; Wl = g_wv_lo; break;
        default: Wh = g_wf_hi; Wl = g_wf_lo; break;
    }

    float acc[2][8][4];
#pragma unroll
    for (int i = 0; i < 2; i++)
#pragma unroll
        for (int j = 0; j < 8; j++)
#pragma unroll
            for (int q = 0; q < 4; q++) acc[i][j][q] = 0.f;

    uint4 rr[8], nn[8];   // [0..3]: A fp32, [4..7]: Wh/Wl bf16

    auto gload = [&](int c, uint4* R) {
        int kk = c * 32;
#pragma unroll
        for (int i = 0; i < 4; i++) {       // A tile fp32: 128 rows x 32 floats
            int id = t + i * 256;
            int row = id >> 3, sg = id & 7;
            R[i] = *(const uint4*)(Ap + (size_t)(mbase + row) * Dm + kk + sg * 4);
        }
#pragma unroll
        for (int i = 0; i < 4; i++) {       // Wh, Wl tiles bf16
            int id = t + i * 256;
            int tile = id >> 9, w = id & 511, row = w >> 2, sg = w & 3;
            const __nv_bfloat16* src = (tile == 0) ? Wh : Wl;
            R[4 + i] = *(const uint4*)(src + (size_t)(nbase + row) * Dm + kk + sg * 8);
        }
    };
    auto gstore = [&](int c, const uint4* R) {
        char* buf = gsm + (c & 1) * GBUF;
#pragma unroll
        for (int i = 0; i < 4; i++) {       // split A fp32 -> Ah/Al
            int id = t + i * 256;
            int row = id >> 3, sg = id & 7;
            float4 v = *(const float4*)&R[i];
            uint2 hi = make_uint2(pk(v.x, v.y), pk(v.z, v.w));
            uint2 lo = make_uint2(pk(resid_f(v.x), resid_f(v.y)), pk(resid_f(v.z), resid_f(v.w)));
            *(uint2*)(buf + row * GP + sg * 8) = hi;
            *(uint2*)(buf + GTILE + row * GP + sg * 8) = lo;
        }
#pragma unroll
        for (int i = 0; i < 4; i++) {
            int id = t + i * 256;
            int tile = id >> 9, w = id & 511, row = w >> 2, sg = w & 3;
            *(uint4*)(buf + (2 + tile) * GTILE + row * GP + sg * 16) = R[4 + i];
        }
    };

    gload(0, rr);

    for (int c = 0; c < 16; c++) {
        gstore(c, rr);
        __syncthreads();
        if (c + 1 < 16) gload(c + 1, nn);

        uint32_t bufu = smem_u32(gsm + (c & 1) * GBUF);
#pragma unroll
        for (int ks = 0; ks < 2; ks++) {
            uint32_t afh[2][4], afl[2][4];
            uint32_t arow = bufu + (wm * 32 + (lane & 15)) * GP + ks * 32 + (lane >> 4) * 16;
            ldsm4(afh[0], arow);
            ldsm4(afh[1], arow + 16 * GP);
            ldsm4(afl[0], arow + GTILE);
            ldsm4(afl[1], arow + GTILE + 16 * GP);
            uint32_t brow = bufu + 2 * GTILE + (wn * 64 + (lane & 15)) * GP + ks * 32 + (lane >> 4) * 16;
            uint32_t wh4[2][4];
            ldsm4(wh4[0], brow);
#pragma unroll
            for (int j2 = 0; j2 < 4; j2++) {
                int cur = j2 & 1;
                uint32_t wl4[4];
                ldsm4(wl4, brow + GTILE + j2 * 16 * GP);         // early: covered by hi-mma block
                if (j2 < 3) ldsm4(wh4[cur ^ 1], brow + (j2 + 1) * 16 * GP);
                {
                    uint32_t be[2] = {wh4[cur][0], wh4[cur][2]}, bo[2] = {wh4[cur][1], wh4[cur][3]};
#pragma unroll
                    for (int i = 0; i < 2; i++) {
                        mma16816(acc[i][2 * j2],     afh[i], be);
                        mma16816(acc[i][2 * j2 + 1], afh[i], bo);
                        mma16816(acc[i][2 * j2],     afl[i], be);
                        mma16816(acc[i][2 * j2 + 1], afl[i], bo);
                    }
                }
                {
                    uint32_t be[2] = {wl4[0], wl4[2]}, bo[2] = {wl4[1], wl4[3]};
#pragma unroll
                    for (int i = 0; i < 2; i++) {
                        mma16816(acc[i][2 * j2],     afh[i], be);
                        mma16816(acc[i][2 * j2 + 1], afh[i], bo);
                    }
                }
            }
        }
#pragma unroll
        for (int i = 0; i < 8; i++) rr[i] = nn[i];
    }

    // epilogue
#pragma unroll
    for (int i = 0; i < 2; i++) {
        int m0 = mbase + wm * 32 + i * 16 + lr;
        int m1 = m0 + 8;
#pragma unroll
        for (int j = 0; j < 8; j++) {
            int n = nbase + wn * 64 + 8 * j + 2 * lc;
            float b0 = bias[n], b1 = bias[n + 1];
            float v0 = acc[i][j][0] + b0, v1 = acc[i][j][1] + b1;   // row m0
            float v2 = acc[i][j][2] + b0, v3 = acc[i][j][3] + b1;   // row m1
            if (mode == 3) {
                size_t o0 = (size_t)m0 * Dm + n, o1 = (size_t)m1 * Dm + n;
                float2 r0 = *(const float2*)(resid + o0);
                float2 r1 = *(const float2*)(resid + o1);
                *(float2*)(g_fc + o0) = make_float2(v0 + r0.x, v1 + r0.y);
                *(float2*)(g_fc + o1) = make_float2(v2 + r1.x, v3 + r1.y);
            } else if (mode == 2) {
                int h = n >> 6, dl = n & 63;
                int b0_ = m0 >> 11, s0 = m0 & (Sq - 1);
                int b1_ = m1 >> 11, s1 = m1 & (Sq - 1);
                size_t p00 = ((size_t)(b0_ * Hh + h) * DKh + dl) * Sq + s0;
                size_t p10 = ((size_t)(b1_ * Hh + h) * DKh + dl) * Sq + s1;
                g_vt_hi[p00] = __float2bfloat16(v0); g_vt_hi[p00 + Sq] = __float2bfloat16(v1);
                g_vt_hi[p10] = __float2bfloat16(v2); g_vt_hi[p10 + Sq] = __float2bfloat16(v3);
            } else {
                int h = n >> 6, dl = n & 63;
                int b0_ = m0 >> 11, s0 = m0 & (Sq - 1);
                int b1_ = m1 >> 11, s1 = m1 & (Sq - 1);
                size_t o0 = ((size_t)(b0_ * Hh + h) * Sq + s0) * DKh + dl;
                size_t o1 = ((size_t)(b1_ * Hh + h) * Sq + s1) * DKh + dl;
                __nv_bfloat16* oh = (mode == 0) ? g_qh_hi : g_kh_hi;
                __nv_bfloat16* ol = (mode == 0) ? g_qh_lo : g_kh_lo;
                *(uint32_t*)(oh + o0) = pk(v0, v1);
                *(uint32_t*)(ol + o0) = pk(resid_f(v0), resid_f(v1));
                *(uint32_t*)(oh + o1) = pk(v2, v3);
                *(uint32_t*)(ol + o1) = pk(resid_f(v2), resid_f(v3));
            }
        }
    }
}

// ======================= flash attention =======================
// grid (16, 32), 256 thr (8 warps). Tq=128 (warp: 16 rows), Tk=64, dk=64.
// S: 3-pass (QhKh + QhKl + QlKh). PV: 2-pass (PhVh + PlVh).
// Fragment loads software-pipelined one step ahead (double-buffered regs) —
// mma order unchanged (bit-identical numerics vs round 12).
#define AP 144
#define ATS 9216          // one k-tile: 64*144
#define ABUF (3*ATS)      // {Kh, Kl, Vh} = 27648
#define QTS  18432        // one Q half: 128*144
#define A_BASE 512
#define AT_SMEM (A_BASE + ABUF + 2*QTS)   // 65024
#define NKT (Sq/64)       // 32

__global__ __launch_bounds__(256, 1) void attn_tc() {
    extern __shared__ char smA[];
    const uint32_t smu = smem_u32(smA);
    const int t = threadIdx.x, lane = t & 31, wid = t >> 5;
    const int lr = lane >> 2, lc = lane & 3;
    const int bh = blockIdx.y, b = bh >> 3;
    const int qbase = blockIdx.x * 128;

    // ---- stage Q (hi/lo) beyond buffer 0, load into registers ----
    {
        char* qdst = smA + A_BASE + ABUF;
#pragma unroll
        for (int i = 0; i < 8; i++) {
            int id = t + i * 256;
            int half = id >> 10, w = id & 1023, row = w >> 3, sg = w & 7;
            const __nv_bfloat16* src = half ? g_qh_lo : g_qh_hi;
            *(uint4*)(qdst + half * QTS + row * AP + sg * 16) =
                *(const uint4*)(src + ((size_t)bh * Sq + qbase + row) * DKh + sg * 8);
        }
    }
    __syncthreads();

    uint32_t qhf[4][4], qlf[4][4];
    {
        uint32_t qb = smu + A_BASE + ABUF + (wid * 16 + (lane & 15)) * AP + (lane >> 4) * 16;
#pragma unroll
        for (int ks = 0; ks < 4; ks++) {
            ldsm4(qhf[ks], qb + ks * 32);
            ldsm4(qlf[ks], qb + ks * 32 + QTS);
        }
    }
    __syncthreads();

    uint4 rv[6], nv[6];
    float rew = 0.f, newv = 0.f;

    auto aload = [&](int kt, uint4* R, float& E) {
#pragma unroll
        for (int i = 0; i < 6; i++) {
            int id = t + i * 256;
            int tile = id >> 9, w = id & 511, row = w >> 3, sg = w & 7;
            const __nv_bfloat16* src;
            size_t g;
            if (tile == 0)      { src = g_kh_hi; g = ((size_t)bh * Sq + kt * 64 + row) * DKh + sg * 8; }
            else if (tile == 1) { src = g_kh_lo; g = ((size_t)bh * Sq + kt * 64 + row) * DKh + sg * 8; }
            else                { src = g_vt_hi; g = ((size_t)bh * DKh + row) * Sq + kt * 64 + sg * 8; }
            R[i] = *(const uint4*)(src + g);
        }
        if (t < 64) E = g_ew[(size_t)b * Sq + kt * 64 + t];
    };
    auto astore = [&](int kt, const uint4* R, float E) {
        char* dst = smA + A_BASE + (kt & 1) * ABUF;
#pragma unroll
        for (int i = 0; i < 6; i++) {
            int id = t + i * 256;
            int tile = id >> 9, w = id & 511, row = w >> 3, sg = w & 7;
            *(uint4*)(dst + tile * ATS + row * AP + sg * 16) = R[i];
        }
        if (t < 64) *(float*)(smA + (kt & 1) * 256 + t * 4) = E;
    };

    float O[8][4];
#pragma unroll
    for (int j = 0; j < 8; j++)
#pragma unroll
        for (int q = 0; q < 4; q++) O[j][q] = 0.f;
    float m0 = -1e30f, m1 = -1e30f, l0 = 0.f, l1 = 0.f;

    aload(0, rv, rew);

    for (int kt = 0; kt < NKT; kt++) {
        astore(kt, rv, rew);
        __syncthreads();
        if (kt + 1 < NKT) aload(kt + 1, nv, newv);

        uint32_t bK = smu + A_BASE + (kt & 1) * ABUF;

        // ---- S = Q K^T : pipelined fragment loads, K fragments reused by Qh/Ql ----
        float S[8][4];
#pragma unroll
        for (int j = 0; j < 8; j++)
#pragma unroll
            for (int q = 0; q < 4; q++) S[j][q] = 0.f;

        uint32_t kbh = bK + (lane & 15) * AP + (lane >> 4) * 16;
        uint32_t kbl = kbh + ATS;
        uint32_t kh4[2][4], kl4[2][4];
        ldsm4(kh4[0], kbh);
        ldsm4(kl4[0], kbl);
#pragma unroll
        for (int idx = 0; idx < 16; idx++) {
            int cur = idx & 1;
            if (idx < 15) {
                uint32_t off = (uint32_t)((idx + 1) & 3) * (16 * AP) + (uint32_t)((idx + 1) >> 2) * 32;
                ldsm4(kh4[cur ^ 1], kbh + off);
                ldsm4(kl4[cur ^ 1], kbl + off);
            }
            int ks = idx >> 2, j2 = idx & 3;
            {
                uint32_t be[2] = {kh4[cur][0], kh4[cur][2]}, bo[2] = {kh4[cur][1], kh4[cur][3]};
                mma16816(S[2 * j2],     qhf[ks], be);
                mma16816(S[2 * j2 + 1], qhf[ks], bo);
                mma16816(S[2 * j2],     qlf[ks], be);
                mma16816(S[2 * j2 + 1], qlf[ks], bo);
            }
            {
                uint32_t be[2] = {kl4[cur][0], kl4[cur][2]}, bo[2] = {kl4[cur][1], kl4[cur][3]};
                mma16816(S[2 * j2],     qhf[ks], be);
                mma16816(S[2 * j2 + 1], qhf[ks], bo);
            }
        }

        // ---- softmax (rows lr and lr+8, cols spread over 4 lanes) ----
        const float* ew = (const float*)(smA + (kt & 1) * 256);
        float mt0 = -1e30f, mt1 = -1e30f;
#pragma unroll
        for (int j = 0; j < 8; j++) {
            float2 e = *(const float2*)(ew + 8 * j + 2 * lc);
            S[j][0] *= e.x; S[j][1] *= e.y;
            S[j][2] *= e.x; S[j][3] *= e.y;
            mt0 = fmaxf(mt0, fmaxf(S[j][0], S[j][1]));
            mt1 = fmaxf(mt1, fmaxf(S[j][2], S[j][3]));
        }
        mt0 = fmaxf(mt0, __shfl_xor_sync(0xffffffffu, mt0, 1));
        mt0 = fmaxf(mt0, __shfl_xor_sync(0xffffffffu, mt0, 2));
        mt1 = fmaxf(mt1, __shfl_xor_sync(0xffffffffu, mt1, 1));
        mt1 = fmaxf(mt1, __shfl_xor_sync(0xffffffffu, mt1, 2));
        float mn0 = fmaxf(m0, mt0), mn1 = fmaxf(m1, mt1);
        float al0 = __expf(m0 - mn0), al1 = __expf(m1 - mn1);
        m0 = mn0; m1 = mn1;
        float ps0 = 0.f, ps1 = 0.f;
#pragma unroll
        for (int j = 0; j < 8; j++) {
            S[j][0] = __expf(S[j][0] - mn0); ps0 += S[j][0];
            S[j][1] = __expf(S[j][1] - mn0); ps0 += S[j][1];
            S[j][2] = __expf(S[j][2] - mn1); ps1 += S[j][2];
            S[j][3] = __expf(S[j][3] - mn1); ps1 += S[j][3];
        }
        ps0 += __shfl_xor_sync(0xffffffffu, ps0, 1);
        ps0 += __shfl_xor_sync(0xffffffffu, ps0, 2);
        ps1 += __shfl_xor_sync(0xffffffffu, ps1, 1);
        ps1 += __shfl_xor_sync(0xffffffffu, ps1, 2);
        l0 = l0 * al0 + ps0;
        l1 = l1 * al1 + ps1;
#pragma unroll
        for (int j = 0; j < 8; j++) {
            O[j][0] *= al0; O[j][1] *= al0;
            O[j][2] *= al1; O[j][3] *= al1;
        }

        // ---- P packs (hi/lo), reused directly as mma A operands ----
        uint32_t Ph[8][2], Pl[8][2];
#pragma unroll
        for (int j = 0; j < 8; j++) {
            Ph[j][0] = pk(S[j][0], S[j][1]);
            Ph[j][1] = pk(S[j][2], S[j][3]);
            Pl[j][0] = pk(resid_f(S[j][0]), resid_f(S[j][1]));
            Pl[j][1] = pk(resid_f(S[j][2]), resid_f(S[j][3]));
        }

        // ---- O += P V : 2-pass, pipelined V fragment loads ----
        uint32_t vbh = bK + 2 * ATS + (lane & 15) * AP + (lane >> 4) * 16;
        uint32_t vh4[2][4];
        ldsm4(vh4[0], vbh);
#pragma unroll
        for (int idx = 0; idx < 16; idx++) {
            int cur = idx & 1;
            if (idx < 15) {
                uint32_t off = (uint32_t)((idx + 1) & 3) * (16 * AP) + (uint32_t)((idx + 1) >> 2) * 32;
                ldsm4(vh4[cur ^ 1], vbh + off);
            }
            int ks = idx >> 2, j2 = idx & 3;
            uint32_t a4h[4] = {Ph[2 * ks][0], Ph[2 * ks][1], Ph[2 * ks + 1][0], Ph[2 * ks + 1][1]};
            uint32_t a4l[4] = {Pl[2 * ks][0], Pl[2 * ks][1], Pl[2 * ks + 1][0], Pl[2 * ks + 1][1]};
            uint32_t ve[2] = {vh4[cur][0], vh4[cur][2]}, vo[2] = {vh4[cur][1], vh4[cur][3]};
            mma16816(O[2 * j2],     a4h, ve);
            mma16816(O[2 * j2 + 1], a4h, vo);
            mma16816(O[2 * j2],     a4l, ve);
            mma16816(O[2 * j2 + 1], a4l, vo);
        }

#pragma unroll
        for (int i = 0; i < 6; i++) rv[i] = nv[i];
        rew = newv;
    }

    // ---- finalize + write fp32 into g_ao (B,S,512) ----
    float inv0 = 1.0f / l0, inv1 = 1.0f / l1;
    int row0 = qbase + wid * 16 + lr, row1 = row0 + 8;
    size_t base0 = ((size_t)(b * Sq + row0)) * Dm + (bh & 7) * DKh + 2 * lc;
    size_t base1 = ((size_t)(b * Sq + row1)) * Dm + (bh & 7) * DKh + 2 * lc;
#pragma unroll
    for (int j = 0; j < 8; j++) {
        *(float2*)(g_ao + base0 + 8 * j) = make_float2(O[j][0] * inv0, O[j][1] * inv0);
        *(float2*)(g_ao + base1 + 8 * j) = make_float2(O[j][2] * inv1, O[j][3] * inv1);
    }
}

// ======================= LayerNorm =======================
__global__ __launch_bounds__(128) void ln_kernel(const float* __restrict__ gamma,
                                                 const float* __restrict__ beta,
                                                 float* __restrict__ out) {
    __shared__ float red[4];
    const int row = blockIdx.x, t = threadIdx.x;
    float4 x = *(const float4*)(g_fc + (size_t)row * Dm + t * 4);
    float s = x.x + x.y + x.z + x.w;
#pragma unroll
    for (int off = 16; off > 0; off >>= 1) s += __shfl_xor_sync(0xffffffffu, s, off);
    if ((t & 31) == 0) red[t >> 5] = s;
    __syncthreads();
    float mu = (red[0] + red[1] + red[2] + red[3]) * (1.0f / Dm);
    float d0 = x.x - mu, d1 = x.y - mu, d2 = x.z - mu, d3 = x.w - mu;
    float sq = d0 * d0 + d1 * d1 + d2 * d2 + d3 * d3;
#pragma unroll
    for (int off = 16; off > 0; off >>= 1) sq += __shfl_xor_sync(0xffffffffu, sq, off);
    __syncthreads();
    if ((t & 31) == 0) red[t >> 5] = sq;
    __syncthreads();
    float var = (red[0] + red[1] + red[2] + red[3]) * (1.0f / Dm);
    float inv = rsqrtf(var + 1e-5f);
    int c = t * 4;
    float4 g = *(const float4*)(gamma + c);
    float4 be = *(const float4*)(beta + c);
    *(float4*)(out + (size_t)row * Dm + c) =
        make_float4(d0 * inv * g.x + be.x, d1 * inv * g.y + be.y,
                    d2 * inv * g.z + be.z, d3 * inv * g.w + be.w);
}

// ======================= launch =======================
extern "C" void kernel_launch(void* const* d_in, const int* in_sizes, int n_in,
                              void* d_out, int out_size) {
    const float* Q   = (const float*)d_in[0];
    const float* K   = (const float*)d_in[1];
    const float* V   = (const float*)d_in[2];
    const float* ent = (const float*)d_in[3];
    const float* Wq  = (const float*)d_in[4];
    const float* bq  = (const float*)d_in[5];
    const float* Wk  = (const float*)d_in[6];
    const float* bk  = (const float*)d_in[7];
    const float* Wv  = (const float*)d_in[8];
    const float* bv  = (const float*)d_in[9];
    const float* Wfc = (const float*)d_in[10];
    const float* bfc = (const float*)d_in[11];
    const float* We  = (const float*)d_in[12];
    const float* gam = (const float*)d_in[13];
    const float* bet = (const float*)d_in[14];
    float* out = (float*)d_out;

    cudaFuncSetAttribute(attn_tc, cudaFuncAttributeMaxDynamicSharedMemorySize, AT_SMEM);
    cudaFuncSetAttribute(gemm_tc, cudaFuncAttributeMaxDynamicSharedMemorySize, GSMEM);

    ew_kernel<<<(Bz * Sq) / 256, 256>>>(We, ent);
    wsplit_kernel<<<dim3(256, 4), 256>>>(Wq, Wk, Wv, Wfc);

    dim3 gg(Dm / 128, Mrows / 128);   // (4, 64)
    gemm_tc<<<gg, 256, GSMEM>>>(Q, bq, nullptr, 0);
    gemm_tc<<<gg, 256, GSMEM>>>(K, bk, nullptr, 1);
    gemm_tc<<<gg, 256, GSMEM>>>(V, bv, nullptr, 2);

    attn_tc<<<dim3(Sq / 128, Bz * Hh), 256, AT_SMEM>>>();

    gemm_tc<<<gg, 256, GSMEM>>>(nullptr, bfc, Q, 3);
    ln_kernel<<<Mrows, 128>>>(gam, bet, out);
}

// round 14
// speedup vs baseline: 2.8208x; 1.0363x over previous
#include <cuda_runtime.h>
#include <cuda_bf16.h>
#include <cstdint>
#include <cstddef>

#define Bz 4
#define Sq 2048
#define Dm 512
#define Hh 8
#define DKh 64
#define Mrows (Bz*Sq)   // 8192

// ======================= scratch (__device__ globals) =======================
__device__ __nv_bfloat16 g_wq_hi[Dm*Dm], g_wq_lo[Dm*Dm];
__device__ __nv_bfloat16 g_wk_hi[Dm*Dm], g_wk_lo[Dm*Dm];
__device__ __nv_bfloat16 g_wv_hi[Dm*Dm], g_wv_lo[Dm*Dm];
__device__ __nv_bfloat16 g_wf_hi[Dm*Dm], g_wf_lo[Dm*Dm];
__device__ __nv_bfloat16 g_qh_hi[Mrows*Dm], g_qh_lo[Mrows*Dm];   // (B,H,S,64)
__device__ __nv_bfloat16 g_kh_hi[Mrows*Dm], g_kh_lo[Mrows*Dm];   // (B,H,S,64)
__device__ __nv_bfloat16 g_vt_hi[Mrows*Dm];                      // (B,H,64,S)
__device__ float g_ao[Mrows*Dm];                                 // attention out fp32 (B,S,D)
__device__ float g_fc[Mrows*Dm];
__device__ float g_ew[Bz*Sq];

// ======================= helpers =======================
__device__ __forceinline__ uint32_t smem_u32(const void* p) {
    uint32_t a;
    asm("{ .reg .u64 t; cvta.to.shared.u64 t, %1; cvt.u32.u64 %0, t; }" : "=r"(a) : "l"(p));
    return a;
}
__device__ __forceinline__ void ldsm4(uint32_t* r, uint32_t addr) {
    asm volatile("ldmatrix.sync.aligned.m8n8.x4.shared.b16 {%0,%1,%2,%3}, [%4];"
        : "=r"(r[0]), "=r"(r[1]), "=r"(r[2]), "=r"(r[3]) : "r"(addr));
}
__device__ __forceinline__ void mma16816(float* d, const uint32_t* a, const uint32_t* b) {
    asm volatile("mma.sync.aligned.m16n8k16.row.col.f32.bf16.bf16.f32 "
        "{%0,%1,%2,%3}, {%4,%5,%6,%7}, {%8,%9}, {%0,%1,%2,%3};"
        : "+f"(d[0]), "+f"(d[1]), "+f"(d[2]), "+f"(d[3])
        : "r"(a[0]), "r"(a[1]), "r"(a[2]), "r"(a[3]), "r"(b[0]), "r"(b[1]));
}
// pack two floats into bf16x2 (v0 -> low half)
__device__ __forceinline__ uint32_t pk(float v0, float v1) {
    uint32_t r;
    asm("cvt.rn.bf16x2.f32 %0, %1, %2;" : "=r"(r) : "f"(v1), "f"(v0));
    return r;
}
__device__ __forceinline__ float resid_f(float v) {
    return v - __bfloat162float(__float2bfloat16(v));
}
__device__ __forceinline__ uint32_t pack_bf2(__nv_bfloat16 a, __nv_bfloat16 b) {
    __nv_bfloat162 v; v.x = a; v.y = b;
    return *reinterpret_cast<uint32_t*>(&v);
}

// ======================= K0: entropy weights =======================
__global__ void ew_kernel(const float* __restrict__ We, const float* __restrict__ ent) {
    int i = blockIdx.x * 256 + threadIdx.x;
    int s = i & (Sq - 1);
    g_ew[i] = 8.0f * __expf(We[s] * ent[i]);
}

// ======================= fused weight splits: fp32 -> bf16 hi/lo =======================
// grid (256, 4): blockIdx.y selects {Wq, Wk, Wv, Wfc}
__global__ void wsplit_kernel(const float* __restrict__ Wq, const float* __restrict__ Wk,
                              const float* __restrict__ Wv, const float* __restrict__ Wfc) {
    int which = blockIdx.y;
    const float* src;
    __nv_bfloat16 *hi, *lo;
    switch (which) {
        case 0: src = Wq;  hi = g_wq_hi; lo = g_wq_lo; break;
        case 1: src = Wk;  hi = g_wk_hi; lo = g_wk_lo; break;
        case 2: src = Wv;  hi = g_wv_hi; lo = g_wv_lo; break;
        default: src = Wfc; hi = g_wf_hi; lo = g_wf_lo; break;
    }
    int i = blockIdx.x * 256 + threadIdx.x;   // i < Dm*Dm/4 = 65536
    float4 v = ((const float4*)src)[i];
    __nv_bfloat16 h0 = __float2bfloat16(v.x), h1 = __float2bfloat16(v.y);
    __nv_bfloat16 h2 = __float2bfloat16(v.z), h3 = __float2bfloat16(v.w);
    __nv_bfloat16 l0 = __float2bfloat16(v.x - __bfloat162float(h0));
    __nv_bfloat16 l1 = __float2bfloat16(v.y - __bfloat162float(h1));
    __nv_bfloat16 l2 = __float2bfloat16(v.z - __bfloat162float(h2));
    __nv_bfloat16 l3 = __float2bfloat16(v.w - __bfloat162float(h3));
    ((uint2*)hi)[i] = make_uint2(pack_bf2(h0, h1), pack_bf2(h2, h3));
    ((uint2*)lo)[i] = make_uint2(pack_bf2(l0, l1), pack_bf2(l2, l3));
}

// ======================= GEMM: C[8192,512] = A * W^T (fused 3-pass hi/lo) =======================
// CTA 128x128, BK=32, 8 warps (4x2), warp tile 32x64.
// OCC=2 design: single smem buffer, NO register prefetch (load->split->store inline),
// latency covered by the co-resident CTA. regs target <=128.
#define GP 80
#define GTILE 10240       // 128 rows x 80B
#define GBUF  (4*GTILE)   // tiles {Ah, Al, Wh, Wl} = 40960
#define GSMEM GBUF

__global__ __launch_bounds__(256, 2) void gemm_tc(const float* __restrict__ Aext,
                                                  const float* __restrict__ bias,
                                                  const float* __restrict__ resid,
                                                  int mode) {
    extern __shared__ __align__(16) char gsm[];
    const int t = threadIdx.x, lane = t & 31, wid = t >> 5;
    const int wm = wid & 3, wn = wid >> 2;
    const int lr = lane >> 2, lc = lane & 3;
    const int mbase = blockIdx.y * 128, nbase = blockIdx.x * 128;

    const float* Ap = (mode == 3) ? g_ao : Aext;
    const __nv_bfloat16 *Wh, *Wl;
    switch (mode) {
        case 0: Wh = g_wq_hi; Wl = g_wq_lo; break;
        case 1: Wh = g_wk_hi; Wl = g_wk_lo; break;
        case 2: Wh = g_wv_hi; Wl = g_wv_lo; break;
        default: Wh = g_wf_hi; Wl = g_wf_lo; break;
    }

    float acc[2][8][4];
#pragma unroll
    for (int i = 0; i < 2; i++)
#pragma unroll
        for (int j = 0; j < 8; j++)
#pragma unroll
            for (int q = 0; q < 4; q++) acc[i][j][q] = 0.f;

    const int a_row = t >> 3, a_sg = t & 7;       // A: 128 rows x 8 segs (uint4 of fp32)
    const int w_row = (t & 511) >> 2, w_sg = t & 3;

    for (int c = 0; c < 16; c++) {
        int kk = c * 32;
        __syncthreads();   // previous iteration's readers done before overwrite
#pragma unroll
        for (int i = 0; i < 4; i++) {       // A fp32 -> split -> {Ah, Al}
            int row = a_row + i * 32;
            float4 v = *(const float4*)(Ap + (size_t)(mbase + row) * Dm + kk + a_sg * 4);
            uint2 hi = make_uint2(pk(v.x, v.y), pk(v.z, v.w));
            uint2 lo = make_uint2(pk(resid_f(v.x), resid_f(v.y)), pk(resid_f(v.z), resid_f(v.w)));
            *(uint2*)(gsm + row * GP + a_sg * 8) = hi;
            *(uint2*)(gsm + GTILE + row * GP + a_sg * 8) = lo;
        }
#pragma unroll
        for (int i = 0; i < 4; i++) {       // Wh, Wl bf16 tiles
            int id = t + i * 256;
            int tile = id >> 9, w = id & 511, row = w >> 2, sg = w & 3;
            const __nv_bfloat16* src = (tile == 0) ? Wh : Wl;
            uint4 vv = *(const uint4*)(src + (size_t)(nbase + row) * Dm + kk + sg * 8);
            *(uint4*)(gsm + (2 + tile) * GTILE + row * GP + sg * 16) = vv;
        }
        __syncthreads();

        uint32_t bufu = smem_u32(gsm);
#pragma unroll
        for (int ks = 0; ks < 2; ks++) {
            uint32_t afh[2][4], afl[2][4];
            uint32_t arow = bufu + (wm * 32 + (lane & 15)) * GP + ks * 32 + (lane >> 4) * 16;
            ldsm4(afh[0], arow);
            ldsm4(afh[1], arow + 16 * GP);
            ldsm4(afl[0], arow + GTILE);
            ldsm4(afl[1], arow + GTILE + 16 * GP);
            uint32_t brow = bufu + 2 * GTILE + (wn * 64 + (lane & 15)) * GP + ks * 32 + (lane >> 4) * 16;
            uint32_t wh4[2][4];
            ldsm4(wh4[0], brow);
#pragma unroll
            for (int j2 = 0; j2 < 4; j2++) {
                int cur = j2 & 1;
                uint32_t wl4[4];
                ldsm4(wl4, brow + GTILE + j2 * 16 * GP);         // early: covered by hi-mma block
                if (j2 < 3) ldsm4(wh4[cur ^ 1], brow + (j2 + 1) * 16 * GP);
                {
                    uint32_t be[2] = {wh4[cur][0], wh4[cur][2]}, bo[2] = {wh4[cur][1], wh4[cur][3]};
#pragma unroll
                    for (int i = 0; i < 2; i++) {
                        mma16816(acc[i][2 * j2],     afh[i], be);
                        mma16816(acc[i][2 * j2 + 1], afh[i], bo);
                        mma16816(acc[i][2 * j2],     afl[i], be);
                        mma16816(acc[i][2 * j2 + 1], afl[i], bo);
                    }
                }
                {
                    uint32_t be[2] = {wl4[0], wl4[2]}, bo[2] = {wl4[1], wl4[3]};
#pragma unroll
                    for (int i = 0; i < 2; i++) {
                        mma16816(acc[i][2 * j2],     afh[i], be);
                        mma16816(acc[i][2 * j2 + 1], afh[i], bo);
                    }
                }
            }
        }
    }

    // epilogue
#pragma unroll
    for (int i = 0; i < 2; i++) {
        int m0 = mbase + wm * 32 + i * 16 + lr;
        int m1 = m0 + 8;
#pragma unroll
        for (int j = 0; j < 8; j++) {
            int n = nbase + wn * 64 + 8 * j + 2 * lc;
            float b0 = bias[n], b1 = bias[n + 1];
            float v0 = acc[i][j][0] + b0, v1 = acc[i][j][1] + b1;   // row m0
            float v2 = acc[i][j][2] + b0, v3 = acc[i][j][3] + b1;   // row m1
            if (mode == 3) {
                size_t o0 = (size_t)m0 * Dm + n, o1 = (size_t)m1 * Dm + n;
                float2 r0 = *(const float2*)(resid + o0);
                float2 r1 = *(const float2*)(resid + o1);
                *(float2*)(g_fc + o0) = make_float2(v0 + r0.x, v1 + r0.y);
                *(float2*)(g_fc + o1) = make_float2(v2 + r1.x, v3 + r1.y);
            } else if (mode == 2) {
                int h = n >> 6, dl = n & 63;
                int b0_ = m0 >> 11, s0 = m0 & (Sq - 1);
                int b1_ = m1 >> 11, s1 = m1 & (Sq - 1);
                size_t p00 = ((size_t)(b0_ * Hh + h) * DKh + dl) * Sq + s0;
                size_t p10 = ((size_t)(b1_ * Hh + h) * DKh + dl) * Sq + s1;
                g_vt_hi[p00] = __float2bfloat16(v0); g_vt_hi[p00 + Sq] = __float2bfloat16(v1);
                g_vt_hi[p10] = __float2bfloat16(v2); g_vt_hi[p10 + Sq] = __float2bfloat16(v3);
            } else {
                int h = n >> 6, dl = n & 63;
                int b0_ = m0 >> 11, s0 = m0 & (Sq - 1);
                int b1_ = m1 >> 11, s1 = m1 & (Sq - 1);
                size_t o0 = ((size_t)(b0_ * Hh + h) * Sq + s0) * DKh + dl;
                size_t o1 = ((size_t)(b1_ * Hh + h) * Sq + s1) * DKh + dl;
                __nv_bfloat16* oh = (mode == 0) ? g_qh_hi : g_kh_hi;
                __nv_bfloat16* ol = (mode == 0) ? g_qh_lo : g_kh_lo;
                *(uint32_t*)(oh + o0) = pk(v0, v1);
                *(uint32_t*)(ol + o0) = pk(resid_f(v0), resid_f(v1));
                *(uint32_t*)(oh + o1) = pk(v2, v3);
                *(uint32_t*)(ol + o1) = pk(resid_f(v2), resid_f(v3));
            }
        }
    }
}

// ======================= flash attention =======================
// grid (16, 32), 256 thr (8 warps). Tq=128 (warp: 16 rows), Tk=64, dk=64.
// S: 3-pass (QhKh + QhKl + QlKh). PV: 2-pass (PhVh + PlVh).
// Fragment loads software-pipelined one step ahead (double-buffered regs).
#define AP 144
#define ATS 9216          // one k-tile: 64*144
#define ABUF (3*ATS)      // {Kh, Kl, Vh} = 27648
#define QTS  18432        // one Q half: 128*144
#define A_BASE 512
#define AT_SMEM (A_BASE + ABUF + 2*QTS)   // 65024
#define NKT (Sq/64)       // 32

__global__ __launch_bounds__(256, 1) void attn_tc() {
    extern __shared__ char smA[];
    const uint32_t smu = smem_u32(smA);
    const int t = threadIdx.x, lane = t & 31, wid = t >> 5;
    const int lr = lane >> 2, lc = lane & 3;
    const int bh = blockIdx.y, b = bh >> 3;
    const int qbase = blockIdx.x * 128;

    // ---- stage Q (hi/lo) beyond buffer 0, load into registers ----
    {
        char* qdst = smA + A_BASE + ABUF;
#pragma unroll
        for (int i = 0; i < 8; i++) {
            int id = t + i * 256;
            int half = id >> 10, w = id & 1023, row = w >> 3, sg = w & 7;
            const __nv_bfloat16* src = half ? g_qh_lo : g_qh_hi;
            *(uint4*)(qdst + half * QTS + row * AP + sg * 16) =
                *(const uint4*)(src + ((size_t)bh * Sq + qbase + row) * DKh + sg * 8);
        }
    }
    __syncthreads();

    uint32_t qhf[4][4], qlf[4][4];
    {
        uint32_t qb = smu + A_BASE + ABUF + (wid * 16 + (lane & 15)) * AP + (lane >> 4) * 16;
#pragma unroll
        for (int ks = 0; ks < 4; ks++) {
            ldsm4(qhf[ks], qb + ks * 32);
            ldsm4(qlf[ks], qb + ks * 32 + QTS);
        }
    }
    __syncthreads();

    uint4 rv[6], nv[6];
    float rew = 0.f, newv = 0.f;

    auto aload = [&](int kt, uint4* R, float& E) {
#pragma unroll
        for (int i = 0; i < 6; i++) {
            int id = t + i * 256;
            int tile = id >> 9, w = id & 511, row = w >> 3, sg = w & 7;
            const __nv_bfloat16* src;
            size_t g;
            if (tile == 0)      { src = g_kh_hi; g = ((size_t)bh * Sq + kt * 64 + row) * DKh + sg * 8; }
            else if (tile == 1) { src = g_kh_lo; g = ((size_t)bh * Sq + kt * 64 + row) * DKh + sg * 8; }
            else                { src = g_vt_hi; g = ((size_t)bh * DKh + row) * Sq + kt * 64 + sg * 8; }
            R[i] = *(const uint4*)(src + g);
        }
        if (t < 64) E = g_ew[(size_t)b * Sq + kt * 64 + t];
    };
    auto astore = [&](int kt, const uint4* R, float E) {
        char* dst = smA + A_BASE + (kt & 1) * ABUF;
#pragma unroll
        for (int i = 0; i < 6; i++) {
            int id = t + i * 256;
            int tile = id >> 9, w = id & 511, row = w >> 3, sg = w & 7;
            *(uint4*)(dst + tile * ATS + row * AP + sg * 16) = R[i];
        }
        if (t < 64) *(float*)(smA + (kt & 1) * 256 + t * 4) = E;
    };

    float O[8][4];
#pragma unroll
    for (int j = 0; j < 8; j++)
#pragma unroll
        for (int q = 0; q < 4; q++) O[j][q] = 0.f;
    float m0 = -1e30f, m1 = -1e30f, l0 = 0.f, l1 = 0.f;

    aload(0, rv, rew);

    for (int kt = 0; kt < NKT; kt++) {
        astore(kt, rv, rew);
        __syncthreads();
        if (kt + 1 < NKT) aload(kt + 1, nv, newv);

        uint32_t bK = smu + A_BASE + (kt & 1) * ABUF;

        // ---- S = Q K^T : pipelined fragment loads, K fragments reused by Qh/Ql ----
        float S[8][4];
#pragma unroll
        for (int j = 0; j < 8; j++)
#pragma unroll
            for (int q = 0; q < 4; q++) S[j][q] = 0.f;

        uint32_t kbh = bK + (lane & 15) * AP + (lane >> 4) * 16;
        uint32_t kbl = kbh + ATS;
        uint32_t kh4[2][4], kl4[2][4];
        ldsm4(kh4[0], kbh);
        ldsm4(kl4[0], kbl);
#pragma unroll
        for (int idx = 0; idx < 16; idx++) {
            int cur = idx & 1;
            if (idx < 15) {
                uint32_t off = (uint32_t)((idx + 1) & 3) * (16 * AP) + (uint32_t)((idx + 1) >> 2) * 32;
                ldsm4(kh4[cur ^ 1], kbh + off);
                ldsm4(kl4[cur ^ 1], kbl + off);
            }
            int ks = idx >> 2, j2 = idx & 3;
            {
                uint32_t be[2] = {kh4[cur][0], kh4[cur][2]}, bo[2] = {kh4[cur][1], kh4[cur][3]};
                mma16816(S[2 * j2],     qhf[ks], be);
                mma16816(S[2 * j2 + 1], qhf[ks], bo);
                mma16816(S[2 * j2],     qlf[ks], be);
                mma16816(S[2 * j2 + 1], qlf[ks], bo);
            }
            {
                uint32_t be[2] = {kl4[cur][0], kl4[cur][2]}, bo[2] = {kl4[cur][1], kl4[cur][3]};
                mma16816(S[2 * j2],     qhf[ks], be);
                mma16816(S[2 * j2 + 1], qhf[ks], bo);
            }
        }

        // ---- softmax (rows lr and lr+8, cols spread over 4 lanes) ----
        const float* ew = (const float*)(smA + (kt & 1) * 256);
        float mt0 = -1e30f, mt1 = -1e30f;
#pragma unroll
        for (int j = 0; j < 8; j++) {
            float2 e = *(const float2*)(ew + 8 * j + 2 * lc);
            S[j][0] *= e.x; S[j][1] *= e.y;
            S[j][2] *= e.x; S[j][3] *= e.y;
            mt0 = fmaxf(mt0, fmaxf(S[j][0], S[j][1]));
            mt1 = fmaxf(mt1, fmaxf(S[j][2], S[j][3]));
        }
        mt0 = fmaxf(mt0, __shfl_xor_sync(0xffffffffu, mt0, 1));
        mt0 = fmaxf(mt0, __shfl_xor_sync(0xffffffffu, mt0, 2));
        mt1 = fmaxf(mt1, __shfl_xor_sync(0xffffffffu, mt1, 1));
        mt1 = fmaxf(mt1, __shfl_xor_sync(0xffffffffu, mt1, 2));
        float mn0 = fmaxf(m0, mt0), mn1 = fmaxf(m1, mt1);
        float al0 = __expf(m0 - mn0), al1 = __expf(m1 - mn1);
        m0 = mn0; m1 = mn1;
        float ps0 = 0.f, ps1 = 0.f;
#pragma unroll
        for (int j = 0; j < 8; j++) {
            S[j][0] = __expf(S[j][0] - mn0); ps0 += S[j][0];
            S[j][1] = __expf(S[j][1] - mn0); ps0 += S[j][1];
            S[j][2] = __expf(S[j][2] - mn1); ps1 += S[j][2];
            S[j][3] = __expf(S[j][3] - mn1); ps1 += S[j][3];
        }
        ps0 += __shfl_xor_sync(0xffffffffu, ps0, 1);
        ps0 += __shfl_xor_sync(0xffffffffu, ps0, 2);
        ps1 += __shfl_xor_sync(0xffffffffu, ps1, 1);
        ps1 += __shfl_xor_sync(0xffffffffu, ps1, 2);
        l0 = l0 * al0 + ps0;
        l1 = l1 * al1 + ps1;
#pragma unroll
        for (int j = 0; j < 8; j++) {
            O[j][0] *= al0; O[j][1] *= al0;
            O[j][2] *= al1; O[j][3] *= al1;
        }

        // ---- P packs (hi/lo), reused directly as mma A operands ----
        uint32_t Ph[8][2], Pl[8][2];
#pragma unroll
        for (int j = 0; j < 8; j++) {
            Ph[j][0] = pk(S[j][0], S[j][1]);
            Ph[j][1] = pk(S[j][2], S[j][3]);
            Pl[j][0] = pk(resid_f(S[j][0]), resid_f(S[j][1]));
            Pl[j][1] = pk(resid_f(S[j][2]), resid_f(S[j][3]));
        }

        // ---- O += P V : 2-pass, pipelined V fragment loads ----
        uint32_t vbh = bK + 2 * ATS + (lane & 15) * AP + (lane >> 4) * 16;
        uint32_t vh4[2][4];
        ldsm4(vh4[0], vbh);
#pragma unroll
        for (int idx = 0; idx < 16; idx++) {
            int cur = idx & 1;
            if (idx < 15) {
                uint32_t off = (uint32_t)((idx + 1) & 3) * (16 * AP) + (uint32_t)((idx + 1) >> 2) * 32;
                ldsm4(vh4[cur ^ 1], vbh + off);
            }
            int ks = idx >> 2, j2 = idx & 3;
            uint32_t a4h[4] = {Ph[2 * ks][0], Ph[2 * ks][1], Ph[2 * ks + 1][0], Ph[2 * ks + 1][1]};
            uint32_t a4l[4] = {Pl[2 * ks][0], Pl[2 * ks][1], Pl[2 * ks + 1][0], Pl[2 * ks + 1][1]};
            uint32_t ve[2] = {vh4[cur][0], vh4[cur][2]}, vo[2] = {vh4[cur][1], vh4[cur][3]};
            mma16816(O[2 * j2],     a4h, ve);
            mma16816(O[2 * j2 + 1], a4h, vo);
            mma16816(O[2 * j2],     a4l, ve);
            mma16816(O[2 * j2 + 1], a4l, vo);
        }

#pragma unroll
        for (int i = 0; i < 6; i++) rv[i] = nv[i];
        rew = newv;
    }

    // ---- finalize + write fp32 into g_ao (B,S,512) ----
    float inv0 = 1.0f / l0, inv1 = 1.0f / l1;
    int row0 = qbase + wid * 16 + lr, row1 = row0 + 8;
    size_t base0 = ((size_t)(b * Sq + row0)) * Dm + (bh & 7) * DKh + 2 * lc;
    size_t base1 = ((size_t)(b * Sq + row1)) * Dm + (bh & 7) * DKh + 2 * lc;
#pragma unroll
    for (int j = 0; j < 8; j++) {
        *(float2*)(g_ao + base0 + 8 * j) = make_float2(O[j][0] * inv0, O[j][1] * inv0);
        *(float2*)(g_ao + base1 + 8 * j) = make_float2(O[j][2] * inv1, O[j][3] * inv1);
    }
}

// ======================= LayerNorm =======================
__global__ __launch_bounds__(128) void ln_kernel(const float* __restrict__ gamma,
                                                 const float* __restrict__ beta,
                                                 float* __restrict__ out) {
    __shared__ float red[4];
    const int row = blockIdx.x, t = threadIdx.x;
    float4 x = *(const float4*)(g_fc + (size_t)row * Dm + t * 4);
    float s = x.x + x.y + x.z + x.w;
#pragma unroll
    for (int off = 16; off > 0; off >>= 1) s += __shfl_xor_sync(0xffffffffu, s, off);
    if ((t & 31) == 0) red[t >> 5] = s;
    __syncthreads();
    float mu = (red[0] + red[1] + red[2] + red[3]) * (1.0f / Dm);
    float d0 = x.x - mu, d1 = x.y - mu, d2 = x.z - mu, d3 = x.w - mu;
    float sq = d0 * d0 + d1 * d1 + d2 * d2 + d3 * d3;
#pragma unroll
    for (int off = 16; off > 0; off >>= 1) sq += __shfl_xor_sync(0xffffffffu, sq, off);
    __syncthreads();
    if ((t & 31) == 0) red[t >> 5] = sq;
    __syncthreads();
    float var = (red[0] + red[1] + red[2] + red[3]) * (1.0f / Dm);
    float inv = rsqrtf(var + 1e-5f);
    int c = t * 4;
    float4 g = *(const float4*)(gamma + c);
    float4 be = *(const float4*)(beta + c);
    *(float4*)(out + (size_t)row * Dm + c) =
        make_float4(d0 * inv * g.x + be.x, d1 * inv * g.y + be.y,
                    d2 * inv * g.z + be.z, d3 * inv * g.w + be.w);
}

// ======================= launch =======================
extern "C" void kernel_launch(void* const* d_in, const int* in_sizes, int n_in,
                              void* d_out, int out_size) {
    const float* Q   = (const float*)d_in[0];
    const float* K   = (const float*)d_in[1];
    const float* V   = (const float*)d_in[2];
    const float* ent = (const float*)d_in[3];
    const float* Wq  = (const float*)d_in[4];
    const float* bq  = (const float*)d_in[5];
    const float* Wk  = (const float*)d_in[6];
    const float* bk  = (const float*)d_in[7];
    const float* Wv  = (const float*)d_in[8];
    const float* bv  = (const float*)d_in[9];
    const float* Wfc = (const float*)d_in[10];
    const float* bfc = (const float*)d_in[11];
    const float* We  = (const float*)d_in[12];
    const float* gam = (const float*)d_in[13];
    const float* bet = (const float*)d_in[14];
    float* out = (float*)d_out;

    cudaFuncSetAttribute(attn_tc, cudaFuncAttributeMaxDynamicSharedMemorySize, AT_SMEM);
    cudaFuncSetAttribute(gemm_tc, cudaFuncAttributeMaxDynamicSharedMemorySize, GSMEM);

    ew_kernel<<<(Bz * Sq) / 256, 256>>>(We, ent);
    wsplit_kernel<<<dim3(256, 4), 256>>>(Wq, Wk, Wv, Wfc);

    dim3 gg(Dm / 128, Mrows / 128);   // (4, 64)
    gemm_tc<<<gg, 256, GSMEM>>>(Q, bq, nullptr, 0);
    gemm_tc<<<gg, 256, GSMEM>>>(K, bk, nullptr, 1);
    gemm_tc<<<gg, 256, GSMEM>>>(V, bv, nullptr, 2);

    attn_tc<<<dim3(Sq / 128, Bz * Hh), 256, AT_SMEM>>>();

    gemm_tc<<<gg, 256, GSMEM>>>(nullptr, bfc, Q, 3);
    ln_kernel<<<Mrows, 128>>>(gam, bet, out);
}